// round 7
// baseline (speedup 1.0000x reference)
#include <cuda_runtime.h>
#include <cstdint>

#define HH 56
#define WW 56
#define WF 29          // 56/2 + 1
#define BB 32
#define CCH 768
#define NBLK 4
#define SPEC (BB*HH*WF*CCH)
#define SSHRINK 0.01f

typedef unsigned long long ull;

// ---------------- scratch (device globals; no allocation allowed) -------------
__device__ float g_Ar[SPEC];
__device__ float g_Ai[SPEC];
__device__ float g_Br[SPEC];
__device__ float g_Bi[SPEC];

// tf32 DFT matrices (padded to mma tiles, pads = 0)
__device__ float g_Ch[64*64],  g_Sh[64*64];    // H-FFT: [k][h], k,h<56
__device__ float g_Cwf[32*64], g_Swfn[32*64];  // fwd rfft W: [kf][w] (Swfn = -sin)
__device__ float g_Cw2[64*32], g_Sw2n[64*32];  // inv rfft W: [w][k] (1/2/1 weights, Sw2n=-a*sin)

// TRANSPOSED expanded weights (B[n][k] = W[k][n]), tf32-rounded: [blk][384][384]
__device__ float g_W1[NBLK*384*384], g_W2[NBLK*384*384];
__device__ float g_b1[NBLK*384],     g_b2[NBLK*384];

__device__ __forceinline__ float to_tf32(float x){
    uint32_t u; asm("cvt.rna.tf32.f32 %0, %1;" : "=r"(u) : "f"(x));
    return __uint_as_float(u);
}
__device__ __forceinline__ uint32_t smem_u32(const void* p) {
    uint32_t a;
    asm("{ .reg .u64 t; cvta.to.shared.u64 t, %1; cvt.u32.u64 %0, t; }" : "=r"(a) : "l"(p));
    return a;
}
#define CP_ASYNC16(sa, gp) \
    asm volatile("cp.async.cg.shared.global [%0], [%1], 16;" :: "r"(sa), "l"(gp))
#define CP_COMMIT() asm volatile("cp.async.commit_group;" ::: "memory")
#define CP_WAIT(n)  asm volatile("cp.async.wait_group %0;" :: "n"(n) : "memory")

__device__ __forceinline__ void mma1688(float c[4], const uint32_t a[4], uint32_t b0, uint32_t b1){
    asm volatile("mma.sync.aligned.m16n8k8.row.col.f32.tf32.tf32.f32 "
        "{%0,%1,%2,%3}, {%4,%5,%6,%7}, {%8,%9}, {%0,%1,%2,%3};"
        : "+f"(c[0]), "+f"(c[1]), "+f"(c[2]), "+f"(c[3])
        : "r"(a[0]), "r"(a[1]), "r"(a[2]), "r"(a[3]), "r"(b0), "r"(b1));
}

// ---------------- init: tf32 DFT matrices + transposed tf32 weights ----------
__global__ void init_k(const float* __restrict__ w1, const float* __restrict__ b1,
                       const float* __restrict__ w2, const float* __restrict__ b2)
{
    int tid = blockIdx.x*blockDim.x + threadIdx.x;
    int nt  = gridDim.x*blockDim.x;
    const double TW  = 6.283185307179586476925286766559 / 56.0;
    const double INV = 0.13363062095621219234827870598923; // 1/sqrt(56)

    for (int i = tid; i < 64*64; i += nt) {
        int k = i >> 6, h = i & 63;
        float c = 0.f, s = 0.f;
        if (k < 56 && h < 56) {
            int m = (k*h) % 56;
            c = to_tf32((float)(cos(TW*m)*INV));
            s = to_tf32((float)(sin(TW*m)*INV));
        }
        g_Ch[i] = c; g_Sh[i] = s;
    }
    for (int i = tid; i < 32*64; i += nt) {
        int kf = i >> 6, w = i & 63;
        float c = 0.f, s = 0.f;
        if (kf < WF && w < 56) {
            int m = (kf*w) % 56;
            c = to_tf32((float)(cos(TW*m)*INV));
            s = to_tf32((float)(-sin(TW*m)*INV));
        }
        g_Cwf[i] = c; g_Swfn[i] = s;
    }
    for (int i = tid; i < 64*32; i += nt) {
        int w = i >> 5, k = i & 31;
        float c = 0.f, s = 0.f;
        if (w < 56 && k < WF) {
            int m = (k*w) % 56;
            double a = (k==0 || k==WF-1) ? 1.0 : 2.0;
            c = to_tf32((float)(a*cos(TW*m)*INV));
            s = to_tf32((float)(-a*sin(TW*m)*INV));
        }
        g_Cw2[i] = c; g_Sw2n[i] = s;
    }
    for (int i = tid; i < NBLK*384*384; i += nt) {
        int blk = i / (384*384);
        int n   = (i / 384) % 384;
        int kd  = i % 384;
        int r = kd, k = n;
        int d  = (r < 192) ? r : r-192;
        int kk = (k < 192) ? k : k-192;
        float v1, v2;
        if (r < 192) {
            if (k < 192) { v1 =  w1[((0*NBLK+blk)*192+d)*192+kk]; v2 =  w2[((0*NBLK+blk)*192+d)*192+kk]; }
            else         { v1 =  w1[((1*NBLK+blk)*192+d)*192+kk]; v2 =  w2[((1*NBLK+blk)*192+d)*192+kk]; }
        } else {
            if (k < 192) { v1 = -w1[((1*NBLK+blk)*192+d)*192+kk]; v2 = -w2[((1*NBLK+blk)*192+d)*192+kk]; }
            else         { v1 =  w1[((0*NBLK+blk)*192+d)*192+kk]; v2 =  w2[((0*NBLK+blk)*192+d)*192+kk]; }
        }
        g_W1[i] = to_tf32(v1); g_W2[i] = to_tf32(v2);
    }
    for (int i = tid; i < NBLK*384; i += nt) {
        int blk = i / 384, k = i % 384;
        g_b1[i] = (k < 192) ? b1[(0*NBLK+blk)*192 + k] : b1[(1*NBLK+blk)*192 + k-192];
        g_b2[i] = (k < 192) ? b2[(0*NBLK+blk)*192 + k] : b2[(1*NBLK+blk)*192 + k-192];
    }
}

// ================= stage 1: rfft along W via tensor mma (K=56, 7 ks) =========
#define RW_C  0
#define RW_S  (32*68)
#define RW_X  (2*32*68)
#define RW_TOT ((2*32*68 + 64*132)*4)

__global__ void __launch_bounds__(256, 2) rfftWT_k(const float* __restrict__ x)
{
    extern __shared__ float sm[];
    float* Cs = sm + RW_C;
    float* Ss = sm + RW_S;
    float* X  = sm + RW_X;
    int bh = blockIdx.x;
    int c0 = blockIdx.y * 128;
    int t  = threadIdx.x;

    for (int i = t; i < 32*64; i += 256) {
        int r = i >> 6, c = i & 63;
        Cs[r*68+c] = g_Cwf[i]; Ss[r*68+c] = g_Swfn[i];
    }
    const float* xp = x + (size_t)bh*WW*CCH + c0;
    for (int i = t; i < 56*32; i += 256) {
        int r = i >> 5, q = i & 31;
        float4 v = *(const float4*)&xp[(size_t)r*CCH + q*4];
        v.x = to_tf32(v.x); v.y = to_tf32(v.y); v.z = to_tf32(v.z); v.w = to_tf32(v.w);
        *(float4*)&X[r*132 + q*4] = v;
    }
    __syncthreads();

    int wid = t >> 5, lane = t & 31, g = lane >> 2, tig = lane & 3;
    int warpM = wid & 1, warpN = wid >> 1;   // 2 x 4
    float cr[4][4], ci[4][4];
    #pragma unroll
    for (int nt=0;nt<4;nt++)
        #pragma unroll
        for (int j=0;j<4;j++){ cr[nt][j]=0.f; ci[nt][j]=0.f; }

    #pragma unroll
    for (int ks = 0; ks < 7; ks++) {
        int row = warpM*16 + g, col = ks*8 + tig;
        uint32_t aC[4], aS[4];
        aC[0]=__float_as_uint(Cs[row*68+col]);     aC[1]=__float_as_uint(Cs[(row+8)*68+col]);
        aC[2]=__float_as_uint(Cs[row*68+col+4]);   aC[3]=__float_as_uint(Cs[(row+8)*68+col+4]);
        aS[0]=__float_as_uint(Ss[row*68+col]);     aS[1]=__float_as_uint(Ss[(row+8)*68+col]);
        aS[2]=__float_as_uint(Ss[row*68+col+4]);   aS[3]=__float_as_uint(Ss[(row+8)*68+col+4]);
        #pragma unroll
        for (int nt = 0; nt < 4; nt++) {
            int n = warpN*32 + nt*8 + g;
            uint32_t b0 = __float_as_uint(X[(ks*8+tig)*132 + n]);
            uint32_t b1 = __float_as_uint(X[(ks*8+tig+4)*132 + n]);
            mma1688(cr[nt], aC, b0, b1);
            mma1688(ci[nt], aS, b0, b1);
        }
    }

    size_t ob = (size_t)bh*WF*CCH + c0;
    #pragma unroll
    for (int nt = 0; nt < 4; nt++) {
        int n2 = warpN*32 + nt*8 + 2*tig;
        int k0r = warpM*16 + g, k1r = k0r + 8;
        *(float2*)&g_Ar[ob + (size_t)k0r*CCH + n2] = make_float2(cr[nt][0], cr[nt][1]);
        *(float2*)&g_Ai[ob + (size_t)k0r*CCH + n2] = make_float2(ci[nt][0], ci[nt][1]);
        if (k1r < WF) {
            *(float2*)&g_Ar[ob + (size_t)k1r*CCH + n2] = make_float2(cr[nt][2], cr[nt][3]);
            *(float2*)&g_Ai[ob + (size_t)k1r*CCH + n2] = make_float2(ci[nt][2], ci[nt][3]);
        }
    }
}

// ================= stage 2/5: complex FFT along H (K=56, 7 ks) ===============
#define FH_C  0
#define FH_S  (64*68)
#define FH_XR (2*64*68)
#define FH_XI (2*64*68 + 64*132)
#define FH_TOT ((2*64*68 + 2*64*132)*4)
#define HROW (WF*CCH)   // 22272

template<int DIR>
__global__ void __launch_bounds__(256, 2) fftHT_k()
{
    extern __shared__ float sm[];
    float* Cs = sm + FH_C;
    float* Ss = sm + FH_S;
    float* XR = sm + FH_XR;
    float* XI = sm + FH_XI;
    int b  = blockIdx.x;
    int j0 = blockIdx.y * 128;
    int t  = threadIdx.x;

    const float* inR  = (DIR==0) ? g_Ar : g_Br;
    const float* inI  = (DIR==0) ? g_Ai : g_Bi;
    float*       outR = (DIR==0) ? g_Br : g_Ar;
    float*       outI = (DIR==0) ? g_Bi : g_Ai;

    for (int i = t; i < 64*64; i += 256) {
        int r = i >> 6, c = i & 63;
        Cs[r*68+c] = g_Ch[i];
        float s = g_Sh[i];
        Ss[r*68+c] = (DIR==0) ? s : -s;
    }
    size_t base = (size_t)b*HH*HROW + j0;
    for (int i = t; i < 56*32; i += 256) {
        int r = i >> 5, q = i & 31;
        float4 vr = *(const float4*)&inR[base + (size_t)r*HROW + q*4];
        float4 vi = *(const float4*)&inI[base + (size_t)r*HROW + q*4];
        vr.x=to_tf32(vr.x); vr.y=to_tf32(vr.y); vr.z=to_tf32(vr.z); vr.w=to_tf32(vr.w);
        vi.x=to_tf32(vi.x); vi.y=to_tf32(vi.y); vi.z=to_tf32(vi.z); vi.w=to_tf32(vi.w);
        *(float4*)&XR[r*132 + q*4] = vr;
        *(float4*)&XI[r*132 + q*4] = vi;
    }
    __syncthreads();

    int wid = t >> 5, lane = t & 31, g = lane >> 2, tig = lane & 3;
    int warpM = wid & 3, warpN = wid >> 2;   // 4 x 2
    float cr[8][4], ci[8][4];
    #pragma unroll
    for (int nt=0;nt<8;nt++)
        #pragma unroll
        for (int j=0;j<4;j++){ cr[nt][j]=0.f; ci[nt][j]=0.f; }

    #pragma unroll
    for (int ks = 0; ks < 7; ks++) {
        int row = warpM*16 + g, col = ks*8 + tig;
        uint32_t aC[4], aS[4], aSn[4];
        aC[0]=__float_as_uint(Cs[row*68+col]);     aC[1]=__float_as_uint(Cs[(row+8)*68+col]);
        aC[2]=__float_as_uint(Cs[row*68+col+4]);   aC[3]=__float_as_uint(Cs[(row+8)*68+col+4]);
        aS[0]=__float_as_uint(Ss[row*68+col]);     aS[1]=__float_as_uint(Ss[(row+8)*68+col]);
        aS[2]=__float_as_uint(Ss[row*68+col+4]);   aS[3]=__float_as_uint(Ss[(row+8)*68+col+4]);
        #pragma unroll
        for (int j=0;j<4;j++) aSn[j] = aS[j] ^ 0x80000000u;
        #pragma unroll
        for (int nt = 0; nt < 8; nt++) {
            int n = warpN*64 + nt*8 + g;
            uint32_t br0 = __float_as_uint(XR[(ks*8+tig)*132 + n]);
            uint32_t br1 = __float_as_uint(XR[(ks*8+tig+4)*132 + n]);
            uint32_t bi0 = __float_as_uint(XI[(ks*8+tig)*132 + n]);
            uint32_t bi1 = __float_as_uint(XI[(ks*8+tig+4)*132 + n]);
            mma1688(cr[nt], aC,  br0, br1);
            mma1688(cr[nt], aS,  bi0, bi1);
            mma1688(ci[nt], aC,  bi0, bi1);
            mma1688(ci[nt], aSn, br0, br1);
        }
    }

    int k0r = warpM*16 + g;
    #pragma unroll
    for (int nt = 0; nt < 8; nt++) {
        int n2 = warpN*64 + nt*8 + 2*tig;
        float2 r0 = make_float2(cr[nt][0], cr[nt][1]);
        float2 i0 = make_float2(ci[nt][0], ci[nt][1]);
        float2 r1 = make_float2(cr[nt][2], cr[nt][3]);
        float2 i1 = make_float2(ci[nt][2], ci[nt][3]);
        if (DIR == 0) {   // feeds cp.async GEMM: pre-round
            r0.x=to_tf32(r0.x); r0.y=to_tf32(r0.y); i0.x=to_tf32(i0.x); i0.y=to_tf32(i0.y);
            r1.x=to_tf32(r1.x); r1.y=to_tf32(r1.y); i1.x=to_tf32(i1.x); i1.y=to_tf32(i1.y);
        }
        *(float2*)&outR[base + (size_t)k0r*HROW + n2] = r0;
        *(float2*)&outI[base + (size_t)k0r*HROW + n2] = i0;
        if (warpM < 3) {
            *(float2*)&outR[base + (size_t)(k0r+8)*HROW + n2] = r1;
            *(float2*)&outI[base + (size_t)(k0r+8)*HROW + n2] = i1;
        }
    }
}

// ================= stage 6: inverse rfft along W via tensor mma ==============
#define IW_C  0
#define IW_S  (64*36)
#define IW_XR (2*64*36)
#define IW_XI (2*64*36 + 32*132)
#define IW_TOT ((2*64*36 + 2*32*132)*4)

__global__ void __launch_bounds__(256, 2) irfftWT_k(float* __restrict__ out)
{
    extern __shared__ float sm[];
    float* Cs = sm + IW_C;
    float* Ss = sm + IW_S;
    float* XR = sm + IW_XR;
    float* XI = sm + IW_XI;
    int bh = blockIdx.x;
    int c0 = blockIdx.y * 128;
    int t  = threadIdx.x;

    for (int i = t; i < 64*32; i += 256) {
        int r = i >> 5, c = i & 31;
        Cs[r*36+c] = g_Cw2[i]; Ss[r*36+c] = g_Sw2n[i];
    }
    size_t base = (size_t)bh*WF*CCH + c0;
    for (int i = t; i < 32*32; i += 256) {
        int r = i >> 5, q = i & 31;
        float4 vr = make_float4(0.f,0.f,0.f,0.f), vi = vr;
        if (r < WF) {
            vr = *(const float4*)&g_Ar[base + (size_t)r*CCH + q*4];
            vi = *(const float4*)&g_Ai[base + (size_t)r*CCH + q*4];
        }
        vr.x=to_tf32(vr.x); vr.y=to_tf32(vr.y); vr.z=to_tf32(vr.z); vr.w=to_tf32(vr.w);
        vi.x=to_tf32(vi.x); vi.y=to_tf32(vi.y); vi.z=to_tf32(vi.z); vi.w=to_tf32(vi.w);
        *(float4*)&XR[r*132 + q*4] = vr;
        *(float4*)&XI[r*132 + q*4] = vi;
    }
    __syncthreads();

    int wid = t >> 5, lane = t & 31, g = lane >> 2, tig = lane & 3;
    int warpM = wid & 3, warpN = wid >> 2;   // 4 x 2
    float co[8][4];
    #pragma unroll
    for (int nt=0;nt<8;nt++)
        #pragma unroll
        for (int j=0;j<4;j++) co[nt][j]=0.f;

    #pragma unroll
    for (int ks = 0; ks < 4; ks++) {
        int row = warpM*16 + g, col = ks*8 + tig;
        uint32_t aC[4], aS[4];
        aC[0]=__float_as_uint(Cs[row*36+col]);     aC[1]=__float_as_uint(Cs[(row+8)*36+col]);
        aC[2]=__float_as_uint(Cs[row*36+col+4]);   aC[3]=__float_as_uint(Cs[(row+8)*36+col+4]);
        aS[0]=__float_as_uint(Ss[row*36+col]);     aS[1]=__float_as_uint(Ss[(row+8)*36+col]);
        aS[2]=__float_as_uint(Ss[row*36+col+4]);   aS[3]=__float_as_uint(Ss[(row+8)*36+col+4]);
        #pragma unroll
        for (int nt = 0; nt < 8; nt++) {
            int n = warpN*64 + nt*8 + g;
            uint32_t br0 = __float_as_uint(XR[(ks*8+tig)*132 + n]);
            uint32_t br1 = __float_as_uint(XR[(ks*8+tig+4)*132 + n]);
            uint32_t bi0 = __float_as_uint(XI[(ks*8+tig)*132 + n]);
            uint32_t bi1 = __float_as_uint(XI[(ks*8+tig+4)*132 + n]);
            mma1688(co[nt], aC, br0, br1);
            mma1688(co[nt], aS, bi0, bi1);
        }
    }

    int w0 = warpM*16 + g;
    size_t ob = (size_t)bh*WW*CCH + c0;
    #pragma unroll
    for (int nt = 0; nt < 8; nt++) {
        int n2 = warpN*64 + nt*8 + 2*tig;
        *(float2*)&out[ob + (size_t)w0*CCH + n2] = make_float2(co[nt][0], co[nt][1]);
        if (warpM < 3)
            *(float2*)&out[ob + (size_t)(w0+8)*CCH + n2] = make_float2(co[nt][2], co[nt][3]);
    }
}

// ========== MLP GEMM: 256x128 tile, 512 thr, 3-stage static pipeline =========
#define GA0 0
#define GA1 9216
#define GA2 18432
#define GB0 27648
#define GB1 32256
#define GB2 36864
#define GBIAS 41472
#define GEMM_SMEM ((41472 + 128)*4)   // 166400 B (1 CTA/SM)

template<int LAYER>
__device__ __forceinline__ void gload(int blk, int p0, int n0, int kc,
                                      uint32_t aS, uint32_t bS, int t)
{
    const float* inR = (LAYER==1) ? g_Br : g_Ar;
    const float* inI = (LAYER==1) ? g_Bi : g_Ai;
    const float* Wt  = ((LAYER==1) ? g_W1 : g_W2) + (size_t)blk*384*384;
    const float* src = (kc < 6) ? inR : inI;
    int koff = blk*192 + ((kc < 6) ? kc*32 : (kc-6)*32);
    int row = t >> 3, q = t & 7;   // row 0..63, q 0..7
    #pragma unroll
    for (int i = 0; i < 4; i++) {
        int r = row + i*64;        // 0..255
        CP_ASYNC16(aS + (uint32_t)(r*36 + q*4)*4, &src[(size_t)(p0+r)*CCH + koff + q*4]);
    }
    int kb = kc*32;
    #pragma unroll
    for (int i = 0; i < 2; i++) {
        int r = row + i*64;        // 0..127
        CP_ASYNC16(bS + (uint32_t)(r*36 + q*4)*4, &Wt[(size_t)(n0+r)*384 + kb + q*4]);
    }
}

__device__ __forceinline__ void gcompute(const float* __restrict__ As,
                                         const float* __restrict__ Bs,
                                         float c[4][4][4],
                                         int warpM, int warpN, int g, int tig)
{
    #pragma unroll
    for (int ks = 0; ks < 4; ks++) {
        uint32_t a[4][4];
        #pragma unroll
        for (int mt = 0; mt < 4; mt++) {
            int r = warpM*64 + mt*16 + g;
            int col = ks*8 + tig;
            a[mt][0] = __float_as_uint(As[r*36 + col]);
            a[mt][1] = __float_as_uint(As[(r+8)*36 + col]);
            a[mt][2] = __float_as_uint(As[r*36 + col + 4]);
            a[mt][3] = __float_as_uint(As[(r+8)*36 + col + 4]);
        }
        #pragma unroll
        for (int nt = 0; nt < 4; nt++) {
            int n = warpN*32 + nt*8 + g;
            uint32_t b0 = __float_as_uint(Bs[n*36 + ks*8 + tig]);
            uint32_t b1 = __float_as_uint(Bs[n*36 + ks*8 + tig + 4]);
            #pragma unroll
            for (int mt = 0; mt < 4; mt++)
                mma1688(c[mt][nt], a[mt], b0, b1);
        }
    }
}

template<int LAYER>
__global__ void __launch_bounds__(512, 1) gemmM_k()
{
    extern __shared__ float sm[];
    uint32_t smem_base = smem_u32(sm);
    int t = threadIdx.x;
    int wid = t >> 5, lane = t & 31;
    int g = lane >> 2, tig = lane & 3;
    int warpM = wid & 3, warpN = wid >> 2;   // 4 x 4
    int p0  = blockIdx.x * 256;
    int n0  = blockIdx.y * 128;
    int blk = blockIdx.z;

    float*       outR = (LAYER==1) ? g_Ar : g_Br;
    float*       outI = (LAYER==1) ? g_Ai : g_Bi;
    const float* bias = ((LAYER==1) ? g_b1 : g_b2) + blk*384;

    for (int i = t; i < 128; i += 512) sm[GBIAS + i] = bias[n0 + i];

    float c[4][4][4];
    #pragma unroll
    for (int mt=0;mt<4;mt++)
        #pragma unroll
        for (int nt=0;nt<4;nt++)
            #pragma unroll
            for (int j=0;j<4;j++) c[mt][nt][j] = 0.f;

    gload<LAYER>(blk, p0, n0, 0, smem_base + GA0*4, smem_base + GB0*4, t);
    CP_COMMIT();
    gload<LAYER>(blk, p0, n0, 1, smem_base + GA1*4, smem_base + GB1*4, t);
    CP_COMMIT();

    #define GEMM_STEP(KC, AOFF, BOFF, NA, NB, DO_LOAD, LAST)                    \
        do {                                                                    \
            if (LAST) { CP_WAIT(0); } else { CP_WAIT(1); }                      \
            __syncthreads();                                                    \
            if (DO_LOAD) {                                                      \
                gload<LAYER>(blk, p0, n0, (KC)+2,                               \
                             smem_base + (NA)*4, smem_base + (NB)*4, t);        \
                CP_COMMIT();                                                    \
            }                                                                   \
            gcompute(sm + (AOFF), sm + (BOFF), c, warpM, warpN, g, tig);        \
        } while (0)

    #pragma unroll 1
    for (int kq = 0; kq < 4; kq++) {
        int kc0 = kq*3;
        GEMM_STEP(kc0+0, GA0, GB0, GA2, GB2, true,     false);
        GEMM_STEP(kc0+1, GA1, GB1, GA0, GB0, (kq < 3), false);
        GEMM_STEP(kc0+2, GA2, GB2, GA1, GB1, (kq < 3), (kq == 3));
    }
    #undef GEMM_STEP

    #pragma unroll
    for (int mt = 0; mt < 4; mt++) {
        #pragma unroll
        for (int rr = 0; rr < 2; rr++) {
            int r = p0 + warpM*64 + mt*16 + rr*8 + g;
            size_t rowoff = (size_t)r*CCH + blk*192;
            #pragma unroll
            for (int nt = 0; nt < 4; nt++) {
                int kl = warpN*32 + nt*8 + 2*tig;
                int ko = n0 + kl;
                float v0 = c[mt][nt][rr*2+0] + sm[GBIAS + kl];
                float v1 = c[mt][nt][rr*2+1] + sm[GBIAS + kl + 1];
                if (LAYER == 1) {
                    v0 = to_tf32(fmaxf(v0, 0.f));
                    v1 = to_tf32(fmaxf(v1, 0.f));
                } else {
                    v0 = (v0 >  SSHRINK) ? v0-SSHRINK : ((v0 < -SSHRINK) ? v0+SSHRINK : 0.f);
                    v1 = (v1 >  SSHRINK) ? v1-SSHRINK : ((v1 < -SSHRINK) ? v1+SSHRINK : 0.f);
                }
                float* dst = (ko < 192) ? outR : outI;
                int kr = (ko < 192) ? ko : ko - 192;
                *(float2*)&dst[rowoff + kr] = make_float2(v0, v1);
            }
        }
    }
}

// ---------------- launch ------------------------------------------------------
extern "C" void kernel_launch(void* const* d_in, const int* in_sizes, int n_in,
                              void* d_out, int out_size)
{
    const float* x  = (const float*)d_in[0];
    const float* w1 = (const float*)d_in[1];
    const float* b1 = (const float*)d_in[2];
    const float* w2 = (const float*)d_in[3];
    const float* b2 = (const float*)d_in[4];
    float* out = (float*)d_out;

    cudaFuncSetAttribute((const void*)rfftWT_k,   cudaFuncAttributeMaxDynamicSharedMemorySize, RW_TOT);
    cudaFuncSetAttribute((const void*)fftHT_k<0>, cudaFuncAttributeMaxDynamicSharedMemorySize, FH_TOT);
    cudaFuncSetAttribute((const void*)fftHT_k<1>, cudaFuncAttributeMaxDynamicSharedMemorySize, FH_TOT);
    cudaFuncSetAttribute((const void*)irfftWT_k,  cudaFuncAttributeMaxDynamicSharedMemorySize, IW_TOT);
    cudaFuncSetAttribute((const void*)gemmM_k<1>, cudaFuncAttributeMaxDynamicSharedMemorySize, GEMM_SMEM);
    cudaFuncSetAttribute((const void*)gemmM_k<2>, cudaFuncAttributeMaxDynamicSharedMemorySize, GEMM_SMEM);

    init_k<<<512, 256>>>(w1, b1, w2, b2);
    rfftWT_k<<<dim3(BB*HH, 6), 256, RW_TOT>>>(x);
    fftHT_k<0><<<dim3(BB, 174), 256, FH_TOT>>>();
    gemmM_k<1><<<dim3(203, 3, NBLK), 512, GEMM_SMEM>>>();
    gemmM_k<2><<<dim3(203, 3, NBLK), 512, GEMM_SMEM>>>();
    fftHT_k<1><<<dim3(BB, 174), 256, FH_TOT>>>();
    irfftWT_k<<<dim3(BB*HH, 6), 256, IW_TOT>>>(out);
}

// round 8
// speedup vs baseline: 1.0179x; 1.0179x over previous
#include <cuda_runtime.h>
#include <cstdint>

#define HH 56
#define WW 56
#define WF 29          // 56/2 + 1
#define BB 32
#define CCH 768
#define NBLK 4
#define SPEC (BB*HH*WF*CCH)
#define SSHRINK 0.01f

typedef unsigned long long ull;

// ---------------- scratch (device globals; no allocation allowed) -------------
__device__ float g_Ar[SPEC];
__device__ float g_Ai[SPEC];
__device__ float g_Br[SPEC];
__device__ float g_Bi[SPEC];

// tf32 DFT matrices (padded to mma tiles, pads = 0)
__device__ float g_Ch[64*64],  g_Sh[64*64];    // H-FFT: [k][h], k,h<56
__device__ float g_Cwf[32*64], g_Swfn[32*64];  // fwd rfft W: [kf][w] (Swfn = -sin)
__device__ float g_Cw2[64*32], g_Sw2n[64*32];  // inv rfft W: [w][k] (1/2/1 weights, Sw2n=-a*sin)

// TRANSPOSED expanded weights, K-permuted within 32-groups for LDS.64 B-frags:
// g_W[blk][n][grp*32 + j] = Wexp[grp*32 + oldk(j)][n], oldk(j)=8*(j>>3)+((j>>1)&3)+4*(j&1)
__device__ float g_W1[NBLK*384*384], g_W2[NBLK*384*384];
__device__ float g_b1[NBLK*384],     g_b2[NBLK*384];

__device__ __forceinline__ float to_tf32(float x){
    uint32_t u; asm("cvt.rna.tf32.f32 %0, %1;" : "=r"(u) : "f"(x));
    return __uint_as_float(u);
}
__device__ __forceinline__ uint32_t smem_u32(const void* p) {
    uint32_t a;
    asm("{ .reg .u64 t; cvta.to.shared.u64 t, %1; cvt.u32.u64 %0, t; }" : "=r"(a) : "l"(p));
    return a;
}
#define CP_ASYNC16(sa, gp) \
    asm volatile("cp.async.cg.shared.global [%0], [%1], 16;" :: "r"(sa), "l"(gp))
#define CP_COMMIT() asm volatile("cp.async.commit_group;" ::: "memory")
#define CP_WAIT(n)  asm volatile("cp.async.wait_group %0;" :: "n"(n) : "memory")

__device__ __forceinline__ void mma1688(float c[4], const uint32_t a[4], uint32_t b0, uint32_t b1){
    asm volatile("mma.sync.aligned.m16n8k8.row.col.f32.tf32.tf32.f32 "
        "{%0,%1,%2,%3}, {%4,%5,%6,%7}, {%8,%9}, {%0,%1,%2,%3};"
        : "+f"(c[0]), "+f"(c[1]), "+f"(c[2]), "+f"(c[3])
        : "r"(a[0]), "r"(a[1]), "r"(a[2]), "r"(a[3]), "r"(b0), "r"(b1));
}

// ---------------- init: tf32 DFT matrices + permuted transposed weights ------
__global__ void init_k(const float* __restrict__ w1, const float* __restrict__ b1,
                       const float* __restrict__ w2, const float* __restrict__ b2)
{
    int tid = blockIdx.x*blockDim.x + threadIdx.x;
    int nt  = gridDim.x*blockDim.x;
    const double TW  = 6.283185307179586476925286766559 / 56.0;
    const double INV = 0.13363062095621219234827870598923; // 1/sqrt(56)

    for (int i = tid; i < 64*64; i += nt) {
        int k = i >> 6, h = i & 63;
        float c = 0.f, s = 0.f;
        if (k < 56 && h < 56) {
            int m = (k*h) % 56;
            c = to_tf32((float)(cos(TW*m)*INV));
            s = to_tf32((float)(sin(TW*m)*INV));
        }
        g_Ch[i] = c; g_Sh[i] = s;
    }
    for (int i = tid; i < 32*64; i += nt) {
        int kf = i >> 6, w = i & 63;
        float c = 0.f, s = 0.f;
        if (kf < WF && w < 56) {
            int m = (kf*w) % 56;
            c = to_tf32((float)(cos(TW*m)*INV));
            s = to_tf32((float)(-sin(TW*m)*INV));
        }
        g_Cwf[i] = c; g_Swfn[i] = s;
    }
    for (int i = tid; i < 64*32; i += nt) {
        int w = i >> 5, k = i & 31;
        float c = 0.f, s = 0.f;
        if (w < 56 && k < WF) {
            int m = (k*w) % 56;
            double a = (k==0 || k==WF-1) ? 1.0 : 2.0;
            c = to_tf32((float)(a*cos(TW*m)*INV));
            s = to_tf32((float)(-a*sin(TW*m)*INV));
        }
        g_Cw2[i] = c; g_Sw2n[i] = s;
    }
    // permuted transposed weights: dest kd -> source input-dim r via in-group perm
    for (int i = tid; i < NBLK*384*384; i += nt) {
        int blk = i / (384*384);
        int n   = (i / 384) % 384;
        int kd  = i % 384;
        int grp = kd >> 5, j = kd & 31;
        int oldk = ((j >> 3) << 3) + ((j >> 1) & 3) + ((j & 1) << 2);
        int r = grp*32 + oldk;   // input dim (expanded, 0..383)
        int k = n;               // output dim
        int d  = (r < 192) ? r : r-192;
        int kk = (k < 192) ? k : k-192;
        float v1, v2;
        if (r < 192) {
            if (k < 192) { v1 =  w1[((0*NBLK+blk)*192+d)*192+kk]; v2 =  w2[((0*NBLK+blk)*192+d)*192+kk]; }
            else         { v1 =  w1[((1*NBLK+blk)*192+d)*192+kk]; v2 =  w2[((1*NBLK+blk)*192+d)*192+kk]; }
        } else {
            if (k < 192) { v1 = -w1[((1*NBLK+blk)*192+d)*192+kk]; v2 = -w2[((1*NBLK+blk)*192+d)*192+kk]; }
            else         { v1 =  w1[((0*NBLK+blk)*192+d)*192+kk]; v2 =  w2[((0*NBLK+blk)*192+d)*192+kk]; }
        }
        g_W1[i] = to_tf32(v1); g_W2[i] = to_tf32(v2);
    }
    for (int i = tid; i < NBLK*384; i += nt) {
        int blk = i / 384, k = i % 384;
        g_b1[i] = (k < 192) ? b1[(0*NBLK+blk)*192 + k] : b1[(1*NBLK+blk)*192 + k-192];
        g_b2[i] = (k < 192) ? b2[(0*NBLK+blk)*192 + k] : b2[(1*NBLK+blk)*192 + k-192];
    }
}

// ================= stage 1: rfft along W via tensor mma (K=56, 7 ks) =========
#define RW_C  0
#define RW_S  (32*68)
#define RW_X  (2*32*68)
#define RW_TOT ((2*32*68 + 64*132)*4)

__global__ void __launch_bounds__(256, 2) rfftWT_k(const float* __restrict__ x)
{
    extern __shared__ float sm[];
    float* Cs = sm + RW_C;
    float* Ss = sm + RW_S;
    float* X  = sm + RW_X;
    int bh = blockIdx.x;
    int c0 = blockIdx.y * 128;
    int t  = threadIdx.x;

    for (int i = t; i < 32*64; i += 256) {
        int r = i >> 6, c = i & 63;
        Cs[r*68+c] = g_Cwf[i]; Ss[r*68+c] = g_Swfn[i];
    }
    const float* xp = x + (size_t)bh*WW*CCH + c0;
    for (int i = t; i < 56*32; i += 256) {
        int r = i >> 5, q = i & 31;
        float4 v = *(const float4*)&xp[(size_t)r*CCH + q*4];
        v.x = to_tf32(v.x); v.y = to_tf32(v.y); v.z = to_tf32(v.z); v.w = to_tf32(v.w);
        *(float4*)&X[r*132 + q*4] = v;
    }
    __syncthreads();

    int wid = t >> 5, lane = t & 31, g = lane >> 2, tig = lane & 3;
    int warpM = wid & 1, warpN = wid >> 1;   // 2 x 4
    float cr[4][4], ci[4][4];
    #pragma unroll
    for (int nt=0;nt<4;nt++)
        #pragma unroll
        for (int j=0;j<4;j++){ cr[nt][j]=0.f; ci[nt][j]=0.f; }

    #pragma unroll
    for (int ks = 0; ks < 7; ks++) {
        int row = warpM*16 + g, col = ks*8 + tig;
        uint32_t aC[4], aS[4];
        aC[0]=__float_as_uint(Cs[row*68+col]);     aC[1]=__float_as_uint(Cs[(row+8)*68+col]);
        aC[2]=__float_as_uint(Cs[row*68+col+4]);   aC[3]=__float_as_uint(Cs[(row+8)*68+col+4]);
        aS[0]=__float_as_uint(Ss[row*68+col]);     aS[1]=__float_as_uint(Ss[(row+8)*68+col]);
        aS[2]=__float_as_uint(Ss[row*68+col+4]);   aS[3]=__float_as_uint(Ss[(row+8)*68+col+4]);
        #pragma unroll
        for (int nt = 0; nt < 4; nt++) {
            int n = warpN*32 + nt*8 + g;
            uint32_t b0 = __float_as_uint(X[(ks*8+tig)*132 + n]);
            uint32_t b1 = __float_as_uint(X[(ks*8+tig+4)*132 + n]);
            mma1688(cr[nt], aC, b0, b1);
            mma1688(ci[nt], aS, b0, b1);
        }
    }

    size_t ob = (size_t)bh*WF*CCH + c0;
    #pragma unroll
    for (int nt = 0; nt < 4; nt++) {
        int n2 = warpN*32 + nt*8 + 2*tig;
        int k0r = warpM*16 + g, k1r = k0r + 8;
        *(float2*)&g_Ar[ob + (size_t)k0r*CCH + n2] = make_float2(cr[nt][0], cr[nt][1]);
        *(float2*)&g_Ai[ob + (size_t)k0r*CCH + n2] = make_float2(ci[nt][0], ci[nt][1]);
        if (k1r < WF) {
            *(float2*)&g_Ar[ob + (size_t)k1r*CCH + n2] = make_float2(cr[nt][2], cr[nt][3]);
            *(float2*)&g_Ai[ob + (size_t)k1r*CCH + n2] = make_float2(ci[nt][2], ci[nt][3]);
        }
    }
}

// ================= stage 2/5: complex FFT along H (K=56, 7 ks) ===============
#define FH_C  0
#define FH_S  (64*68)
#define FH_XR (2*64*68)
#define FH_XI (2*64*68 + 64*132)
#define FH_TOT ((2*64*68 + 2*64*132)*4)
#define HROW (WF*CCH)   // 22272

template<int DIR>
__global__ void __launch_bounds__(256, 2) fftHT_k()
{
    extern __shared__ float sm[];
    float* Cs = sm + FH_C;
    float* Ss = sm + FH_S;
    float* XR = sm + FH_XR;
    float* XI = sm + FH_XI;
    int b  = blockIdx.x;
    int j0 = blockIdx.y * 128;
    int t  = threadIdx.x;

    const float* inR  = (DIR==0) ? g_Ar : g_Br;
    const float* inI  = (DIR==0) ? g_Ai : g_Bi;
    float*       outR = (DIR==0) ? g_Br : g_Ar;
    float*       outI = (DIR==0) ? g_Bi : g_Ai;

    for (int i = t; i < 64*64; i += 256) {
        int r = i >> 6, c = i & 63;
        Cs[r*68+c] = g_Ch[i];
        float s = g_Sh[i];
        Ss[r*68+c] = (DIR==0) ? s : -s;
    }
    size_t base = (size_t)b*HH*HROW + j0;
    for (int i = t; i < 56*32; i += 256) {
        int r = i >> 5, q = i & 31;
        float4 vr = *(const float4*)&inR[base + (size_t)r*HROW + q*4];
        float4 vi = *(const float4*)&inI[base + (size_t)r*HROW + q*4];
        vr.x=to_tf32(vr.x); vr.y=to_tf32(vr.y); vr.z=to_tf32(vr.z); vr.w=to_tf32(vr.w);
        vi.x=to_tf32(vi.x); vi.y=to_tf32(vi.y); vi.z=to_tf32(vi.z); vi.w=to_tf32(vi.w);
        *(float4*)&XR[r*132 + q*4] = vr;
        *(float4*)&XI[r*132 + q*4] = vi;
    }
    __syncthreads();

    int wid = t >> 5, lane = t & 31, g = lane >> 2, tig = lane & 3;
    int warpM = wid & 3, warpN = wid >> 2;   // 4 x 2
    float cr[8][4], ci[8][4];
    #pragma unroll
    for (int nt=0;nt<8;nt++)
        #pragma unroll
        for (int j=0;j<4;j++){ cr[nt][j]=0.f; ci[nt][j]=0.f; }

    #pragma unroll
    for (int ks = 0; ks < 7; ks++) {
        int row = warpM*16 + g, col = ks*8 + tig;
        uint32_t aC[4], aS[4], aSn[4];
        aC[0]=__float_as_uint(Cs[row*68+col]);     aC[1]=__float_as_uint(Cs[(row+8)*68+col]);
        aC[2]=__float_as_uint(Cs[row*68+col+4]);   aC[3]=__float_as_uint(Cs[(row+8)*68+col+4]);
        aS[0]=__float_as_uint(Ss[row*68+col]);     aS[1]=__float_as_uint(Ss[(row+8)*68+col]);
        aS[2]=__float_as_uint(Ss[row*68+col+4]);   aS[3]=__float_as_uint(Ss[(row+8)*68+col+4]);
        #pragma unroll
        for (int j=0;j<4;j++) aSn[j] = aS[j] ^ 0x80000000u;
        #pragma unroll
        for (int nt = 0; nt < 8; nt++) {
            int n = warpN*64 + nt*8 + g;
            uint32_t br0 = __float_as_uint(XR[(ks*8+tig)*132 + n]);
            uint32_t br1 = __float_as_uint(XR[(ks*8+tig+4)*132 + n]);
            uint32_t bi0 = __float_as_uint(XI[(ks*8+tig)*132 + n]);
            uint32_t bi1 = __float_as_uint(XI[(ks*8+tig+4)*132 + n]);
            mma1688(cr[nt], aC,  br0, br1);
            mma1688(cr[nt], aS,  bi0, bi1);
            mma1688(ci[nt], aC,  bi0, bi1);
            mma1688(ci[nt], aSn, br0, br1);
        }
    }

    int k0r = warpM*16 + g;
    #pragma unroll
    for (int nt = 0; nt < 8; nt++) {
        int n2 = warpN*64 + nt*8 + 2*tig;
        float2 r0 = make_float2(cr[nt][0], cr[nt][1]);
        float2 i0 = make_float2(ci[nt][0], ci[nt][1]);
        float2 r1 = make_float2(cr[nt][2], cr[nt][3]);
        float2 i1 = make_float2(ci[nt][2], ci[nt][3]);
        if (DIR == 0) {   // feeds cp.async GEMM: pre-round
            r0.x=to_tf32(r0.x); r0.y=to_tf32(r0.y); i0.x=to_tf32(i0.x); i0.y=to_tf32(i0.y);
            r1.x=to_tf32(r1.x); r1.y=to_tf32(r1.y); i1.x=to_tf32(i1.x); i1.y=to_tf32(i1.y);
        }
        *(float2*)&outR[base + (size_t)k0r*HROW + n2] = r0;
        *(float2*)&outI[base + (size_t)k0r*HROW + n2] = i0;
        if (warpM < 3) {
            *(float2*)&outR[base + (size_t)(k0r+8)*HROW + n2] = r1;
            *(float2*)&outI[base + (size_t)(k0r+8)*HROW + n2] = i1;
        }
    }
}

// ================= stage 6: inverse rfft along W via tensor mma ==============
#define IW_C  0
#define IW_S  (64*36)
#define IW_XR (2*64*36)
#define IW_XI (2*64*36 + 32*132)
#define IW_TOT ((2*64*36 + 2*32*132)*4)

__global__ void __launch_bounds__(256, 2) irfftWT_k(float* __restrict__ out)
{
    extern __shared__ float sm[];
    float* Cs = sm + IW_C;
    float* Ss = sm + IW_S;
    float* XR = sm + IW_XR;
    float* XI = sm + IW_XI;
    int bh = blockIdx.x;
    int c0 = blockIdx.y * 128;
    int t  = threadIdx.x;

    for (int i = t; i < 64*32; i += 256) {
        int r = i >> 5, c = i & 31;
        Cs[r*36+c] = g_Cw2[i]; Ss[r*36+c] = g_Sw2n[i];
    }
    size_t base = (size_t)bh*WF*CCH + c0;
    for (int i = t; i < 32*32; i += 256) {
        int r = i >> 5, q = i & 31;
        float4 vr = make_float4(0.f,0.f,0.f,0.f), vi = vr;
        if (r < WF) {
            vr = *(const float4*)&g_Ar[base + (size_t)r*CCH + q*4];
            vi = *(const float4*)&g_Ai[base + (size_t)r*CCH + q*4];
        }
        vr.x=to_tf32(vr.x); vr.y=to_tf32(vr.y); vr.z=to_tf32(vr.z); vr.w=to_tf32(vr.w);
        vi.x=to_tf32(vi.x); vi.y=to_tf32(vi.y); vi.z=to_tf32(vi.z); vi.w=to_tf32(vi.w);
        *(float4*)&XR[r*132 + q*4] = vr;
        *(float4*)&XI[r*132 + q*4] = vi;
    }
    __syncthreads();

    int wid = t >> 5, lane = t & 31, g = lane >> 2, tig = lane & 3;
    int warpM = wid & 3, warpN = wid >> 2;   // 4 x 2
    float co[8][4];
    #pragma unroll
    for (int nt=0;nt<8;nt++)
        #pragma unroll
        for (int j=0;j<4;j++) co[nt][j]=0.f;

    #pragma unroll
    for (int ks = 0; ks < 4; ks++) {
        int row = warpM*16 + g, col = ks*8 + tig;
        uint32_t aC[4], aS[4];
        aC[0]=__float_as_uint(Cs[row*36+col]);     aC[1]=__float_as_uint(Cs[(row+8)*36+col]);
        aC[2]=__float_as_uint(Cs[row*36+col+4]);   aC[3]=__float_as_uint(Cs[(row+8)*36+col+4]);
        aS[0]=__float_as_uint(Ss[row*36+col]);     aS[1]=__float_as_uint(Ss[(row+8)*36+col]);
        aS[2]=__float_as_uint(Ss[row*36+col+4]);   aS[3]=__float_as_uint(Ss[(row+8)*36+col+4]);
        #pragma unroll
        for (int nt = 0; nt < 8; nt++) {
            int n = warpN*64 + nt*8 + g;
            uint32_t br0 = __float_as_uint(XR[(ks*8+tig)*132 + n]);
            uint32_t br1 = __float_as_uint(XR[(ks*8+tig+4)*132 + n]);
            uint32_t bi0 = __float_as_uint(XI[(ks*8+tig)*132 + n]);
            uint32_t bi1 = __float_as_uint(XI[(ks*8+tig+4)*132 + n]);
            mma1688(co[nt], aC, br0, br1);
            mma1688(co[nt], aS, bi0, bi1);
        }
    }

    int w0 = warpM*16 + g;
    size_t ob = (size_t)bh*WW*CCH + c0;
    #pragma unroll
    for (int nt = 0; nt < 8; nt++) {
        int n2 = warpN*64 + nt*8 + 2*tig;
        *(float2*)&out[ob + (size_t)w0*CCH + n2] = make_float2(co[nt][0], co[nt][1]);
        if (warpM < 3)
            *(float2*)&out[ob + (size_t)(w0+8)*CCH + n2] = make_float2(co[nt][2], co[nt][3]);
    }
}

// ========== MLP GEMM: 128x128, 256 thr, 2 CTA/SM, 3-stage, LDS.64 B-frags ====
#define GA0 0
#define GA1 4608
#define GA2 9216
#define GB0 13824
#define GB1 18432
#define GB2 23040
#define GBIAS 27648
#define GEMM_SMEM ((27648 + 128)*4)   // 111104 B (2 CTAs/SM)

template<int LAYER>
__device__ __forceinline__ void gload(int blk, int p0, int n0, int kc,
                                      uint32_t aS, uint32_t bS, int t)
{
    const float* inR = (LAYER==1) ? g_Br : g_Ar;
    const float* inI = (LAYER==1) ? g_Bi : g_Ai;
    const float* Wt  = ((LAYER==1) ? g_W1 : g_W2) + (size_t)blk*384*384;
    const float* src = (kc < 6) ? inR : inI;
    int koff = blk*192 + ((kc < 6) ? kc*32 : (kc-6)*32);
    int row = t >> 3, q = t & 7;
    #pragma unroll
    for (int i = 0; i < 4; i++) {
        int r = row + i*32;
        CP_ASYNC16(aS + (uint32_t)(r*36 + q*4)*4, &src[(size_t)(p0+r)*CCH + koff + q*4]);
    }
    int kb = kc*32;
    #pragma unroll
    for (int i = 0; i < 4; i++) {
        int r = row + i*32;
        CP_ASYNC16(bS + (uint32_t)(r*36 + q*4)*4, &Wt[(size_t)(n0+r)*384 + kb + q*4]);
    }
}

__device__ __forceinline__ void gcompute(const float* __restrict__ As,
                                         const float* __restrict__ Bs,
                                         float c[2][8][4],
                                         int warpM, int warpN, int g, int tig)
{
    #pragma unroll
    for (int ks = 0; ks < 4; ks++) {
        uint32_t a[2][4];
        #pragma unroll
        for (int mt = 0; mt < 2; mt++) {
            int r = warpM*32 + mt*16 + g;
            int col = ks*8 + tig;
            a[mt][0] = __float_as_uint(As[r*36 + col]);
            a[mt][1] = __float_as_uint(As[(r+8)*36 + col]);
            a[mt][2] = __float_as_uint(As[r*36 + col + 4]);
            a[mt][3] = __float_as_uint(As[(r+8)*36 + col + 4]);
        }
        #pragma unroll
        for (int nt = 0; nt < 8; nt++) {
            int n = warpN*64 + nt*8 + g;
            // W pre-permuted: (k, k+4) adjacent -> single LDS.64
            float2 bb = *(const float2*)&Bs[n*36 + (ks*4 + tig)*2];
            uint32_t b0 = __float_as_uint(bb.x);
            uint32_t b1 = __float_as_uint(bb.y);
            mma1688(c[0][nt], a[0], b0, b1);
            mma1688(c[1][nt], a[1], b0, b1);
        }
    }
}

template<int LAYER>
__global__ void __launch_bounds__(256, 2) gemmM_k()
{
    extern __shared__ float sm[];
    uint32_t smem_base = smem_u32(sm);
    int t = threadIdx.x;
    int wid = t >> 5, lane = t & 31;
    int g = lane >> 2, tig = lane & 3;
    int warpM = wid & 3, warpN = wid >> 2;
    int p0  = blockIdx.x * 128;
    int n0  = blockIdx.y * 128;
    int blk = blockIdx.z;

    float*       outR = (LAYER==1) ? g_Ar : g_Br;
    float*       outI = (LAYER==1) ? g_Ai : g_Bi;
    const float* bias = ((LAYER==1) ? g_b1 : g_b2) + blk*384;

    for (int i = t; i < 128; i += 256) sm[GBIAS + i] = bias[n0 + i];

    float c[2][8][4];
    #pragma unroll
    for (int mt=0;mt<2;mt++)
        #pragma unroll
        for (int nt=0;nt<8;nt++)
            #pragma unroll
            for (int j=0;j<4;j++) c[mt][nt][j] = 0.f;

    gload<LAYER>(blk, p0, n0, 0, smem_base + GA0*4, smem_base + GB0*4, t);
    CP_COMMIT();
    gload<LAYER>(blk, p0, n0, 1, smem_base + GA1*4, smem_base + GB1*4, t);
    CP_COMMIT();

    #define GEMM_STEP(KC, AOFF, BOFF, NA, NB, DO_LOAD, LAST)                    \
        do {                                                                    \
            if (LAST) { CP_WAIT(0); } else { CP_WAIT(1); }                      \
            __syncthreads();                                                    \
            if (DO_LOAD) {                                                      \
                gload<LAYER>(blk, p0, n0, (KC)+2,                               \
                             smem_base + (NA)*4, smem_base + (NB)*4, t);        \
                CP_COMMIT();                                                    \
            }                                                                   \
            gcompute(sm + (AOFF), sm + (BOFF), c, warpM, warpN, g, tig);        \
        } while (0)

    #pragma unroll 1
    for (int kq = 0; kq < 4; kq++) {
        int kc0 = kq*3;
        GEMM_STEP(kc0+0, GA0, GB0, GA2, GB2, true,     false);
        GEMM_STEP(kc0+1, GA1, GB1, GA0, GB0, (kq < 3), false);
        GEMM_STEP(kc0+2, GA2, GB2, GA1, GB1, (kq < 3), (kq == 3));
    }
    #undef GEMM_STEP

    #pragma unroll
    for (int mt = 0; mt < 2; mt++) {
        #pragma unroll
        for (int rr = 0; rr < 2; rr++) {
            int r = p0 + warpM*32 + mt*16 + rr*8 + g;
            size_t rowoff = (size_t)r*CCH + blk*192;
            #pragma unroll
            for (int nt = 0; nt < 8; nt++) {
                int kl = warpN*64 + nt*8 + 2*tig;
                int ko = n0 + kl;
                float v0 = c[mt][nt][rr*2+0] + sm[GBIAS + kl];
                float v1 = c[mt][nt][rr*2+1] + sm[GBIAS + kl + 1];
                if (LAYER == 1) {
                    v0 = to_tf32(fmaxf(v0, 0.f));
                    v1 = to_tf32(fmaxf(v1, 0.f));
                } else {
                    v0 = (v0 >  SSHRINK) ? v0-SSHRINK : ((v0 < -SSHRINK) ? v0+SSHRINK : 0.f);
                    v1 = (v1 >  SSHRINK) ? v1-SSHRINK : ((v1 < -SSHRINK) ? v1+SSHRINK : 0.f);
                }
                float* dst = (ko < 192) ? outR : outI;
                int kr = (ko < 192) ? ko : ko - 192;
                *(float2*)&dst[rowoff + kr] = make_float2(v0, v1);
            }
        }
    }
}

// ---------------- launch ------------------------------------------------------
extern "C" void kernel_launch(void* const* d_in, const int* in_sizes, int n_in,
                              void* d_out, int out_size)
{
    const float* x  = (const float*)d_in[0];
    const float* w1 = (const float*)d_in[1];
    const float* b1 = (const float*)d_in[2];
    const float* w2 = (const float*)d_in[3];
    const float* b2 = (const float*)d_in[4];
    float* out = (float*)d_out;

    cudaFuncSetAttribute((const void*)rfftWT_k,   cudaFuncAttributeMaxDynamicSharedMemorySize, RW_TOT);
    cudaFuncSetAttribute((const void*)fftHT_k<0>, cudaFuncAttributeMaxDynamicSharedMemorySize, FH_TOT);
    cudaFuncSetAttribute((const void*)fftHT_k<1>, cudaFuncAttributeMaxDynamicSharedMemorySize, FH_TOT);
    cudaFuncSetAttribute((const void*)irfftWT_k,  cudaFuncAttributeMaxDynamicSharedMemorySize, IW_TOT);
    cudaFuncSetAttribute((const void*)gemmM_k<1>, cudaFuncAttributeMaxDynamicSharedMemorySize, GEMM_SMEM);
    cudaFuncSetAttribute((const void*)gemmM_k<2>, cudaFuncAttributeMaxDynamicSharedMemorySize, GEMM_SMEM);

    init_k<<<512, 256>>>(w1, b1, w2, b2);
    rfftWT_k<<<dim3(BB*HH, 6), 256, RW_TOT>>>(x);
    fftHT_k<0><<<dim3(BB, 174), 256, FH_TOT>>>();
    gemmM_k<1><<<dim3(406, 3, NBLK), 256, GEMM_SMEM>>>();
    gemmM_k<2><<<dim3(406, 3, NBLK), 256, GEMM_SMEM>>>();
    fftHT_k<1><<<dim3(BB, 174), 256, FH_TOT>>>();
    irfftWT_k<<<dim3(BB*HH, 6), 256, IW_TOT>>>(out);
}

// round 9
// speedup vs baseline: 1.0653x; 1.0466x over previous
#include <cuda_runtime.h>
#include <cstdint>

#define HH 56
#define WW 56
#define WF 29          // 56/2 + 1
#define BB 32
#define CCH 768
#define NBLK 4
#define SPEC (BB*HH*WF*CCH)
#define SSHRINK 0.01f

typedef unsigned long long ull;

// ---------------- scratch (device globals; no allocation allowed) -------------
__device__ float g_Ar[SPEC];
__device__ float g_Ai[SPEC];
__device__ float g_Br[SPEC];
__device__ float g_Bi[SPEC];

// tf32 DFT matrices (padded to mma tiles, pads = 0)
__device__ float g_Ch[64*64],  g_Sh[64*64];    // H-FFT: [k][h], k,h<56
__device__ float g_Cwf[32*64], g_Swfn[32*64];  // fwd rfft W: [kf][w] (Swfn = -sin)
__device__ float g_Cw2[64*32], g_Sw2n[64*32];  // inv rfft W: [w][k] (1/2/1 weights, Sw2n=-a*sin)

// TRANSPOSED expanded weights (B[n][k] = W[k][n]), tf32-rounded: [blk][384][384]
__device__ float g_W1[NBLK*384*384], g_W2[NBLK*384*384];
__device__ float g_b1[NBLK*384],     g_b2[NBLK*384];

__device__ __forceinline__ float to_tf32(float x){
    uint32_t u; asm("cvt.rna.tf32.f32 %0, %1;" : "=r"(u) : "f"(x));
    return __uint_as_float(u);
}
__device__ __forceinline__ uint32_t smem_u32(const void* p) {
    uint32_t a;
    asm("{ .reg .u64 t; cvta.to.shared.u64 t, %1; cvt.u32.u64 %0, t; }" : "=r"(a) : "l"(p));
    return a;
}
#define CP_ASYNC16(sa, gp) \
    asm volatile("cp.async.cg.shared.global [%0], [%1], 16;" :: "r"(sa), "l"(gp))
#define CP_COMMIT() asm volatile("cp.async.commit_group;" ::: "memory")
#define CP_WAIT(n)  asm volatile("cp.async.wait_group %0;" :: "n"(n) : "memory")

__device__ __forceinline__ void mma1688(float c[4], const uint32_t a[4], uint32_t b0, uint32_t b1){
    asm volatile("mma.sync.aligned.m16n8k8.row.col.f32.tf32.tf32.f32 "
        "{%0,%1,%2,%3}, {%4,%5,%6,%7}, {%8,%9}, {%0,%1,%2,%3};"
        : "+f"(c[0]), "+f"(c[1]), "+f"(c[2]), "+f"(c[3])
        : "r"(a[0]), "r"(a[1]), "r"(a[2]), "r"(a[3]), "r"(b0), "r"(b1));
}

// ---------------- init: tf32 DFT matrices + transposed tf32 weights ----------
__global__ void init_k(const float* __restrict__ w1, const float* __restrict__ b1,
                       const float* __restrict__ w2, const float* __restrict__ b2)
{
    int tid = blockIdx.x*blockDim.x + threadIdx.x;
    int nt  = gridDim.x*blockDim.x;
    const double TW  = 6.283185307179586476925286766559 / 56.0;
    const double INV = 0.13363062095621219234827870598923; // 1/sqrt(56)

    for (int i = tid; i < 64*64; i += nt) {
        int k = i >> 6, h = i & 63;
        float c = 0.f, s = 0.f;
        if (k < 56 && h < 56) {
            int m = (k*h) % 56;
            c = to_tf32((float)(cos(TW*m)*INV));
            s = to_tf32((float)(sin(TW*m)*INV));
        }
        g_Ch[i] = c; g_Sh[i] = s;
    }
    for (int i = tid; i < 32*64; i += nt) {
        int kf = i >> 6, w = i & 63;
        float c = 0.f, s = 0.f;
        if (kf < WF && w < 56) {
            int m = (kf*w) % 56;
            c = to_tf32((float)(cos(TW*m)*INV));
            s = to_tf32((float)(-sin(TW*m)*INV));
        }
        g_Cwf[i] = c; g_Swfn[i] = s;
    }
    for (int i = tid; i < 64*32; i += nt) {
        int w = i >> 5, k = i & 31;
        float c = 0.f, s = 0.f;
        if (w < 56 && k < WF) {
            int m = (k*w) % 56;
            double a = (k==0 || k==WF-1) ? 1.0 : 2.0;
            c = to_tf32((float)(a*cos(TW*m)*INV));
            s = to_tf32((float)(-a*sin(TW*m)*INV));
        }
        g_Cw2[i] = c; g_Sw2n[i] = s;
    }
    for (int i = tid; i < NBLK*384*384; i += nt) {
        int blk = i / (384*384);
        int n   = (i / 384) % 384;
        int kd  = i % 384;
        int r = kd, k = n;
        int d  = (r < 192) ? r : r-192;
        int kk = (k < 192) ? k : k-192;
        float v1, v2;
        if (r < 192) {
            if (k < 192) { v1 =  w1[((0*NBLK+blk)*192+d)*192+kk]; v2 =  w2[((0*NBLK+blk)*192+d)*192+kk]; }
            else         { v1 =  w1[((1*NBLK+blk)*192+d)*192+kk]; v2 =  w2[((1*NBLK+blk)*192+d)*192+kk]; }
        } else {
            if (k < 192) { v1 = -w1[((1*NBLK+blk)*192+d)*192+kk]; v2 = -w2[((1*NBLK+blk)*192+d)*192+kk]; }
            else         { v1 =  w1[((0*NBLK+blk)*192+d)*192+kk]; v2 =  w2[((0*NBLK+blk)*192+d)*192+kk]; }
        }
        g_W1[i] = to_tf32(v1); g_W2[i] = to_tf32(v2);
    }
    for (int i = tid; i < NBLK*384; i += nt) {
        int blk = i / 384, k = i % 384;
        g_b1[i] = (k < 192) ? b1[(0*NBLK+blk)*192 + k] : b1[(1*NBLK+blk)*192 + k-192];
        g_b2[i] = (k < 192) ? b2[(0*NBLK+blk)*192 + k] : b2[(1*NBLK+blk)*192 + k-192];
    }
}

// ================= stage 1: rfft along W via tensor mma (K=56, 7 ks) =========
#define RW_C  0
#define RW_S  (32*68)
#define RW_X  (2*32*68)
#define RW_TOT ((2*32*68 + 64*132)*4)

__global__ void __launch_bounds__(256, 2) rfftWT_k(const float* __restrict__ x)
{
    extern __shared__ float sm[];
    float* Cs = sm + RW_C;
    float* Ss = sm + RW_S;
    float* X  = sm + RW_X;
    int bh = blockIdx.x;
    int c0 = blockIdx.y * 128;
    int t  = threadIdx.x;

    for (int i = t; i < 32*64; i += 256) {
        int r = i >> 6, c = i & 63;
        Cs[r*68+c] = g_Cwf[i]; Ss[r*68+c] = g_Swfn[i];
    }
    const float* xp = x + (size_t)bh*WW*CCH + c0;
    for (int i = t; i < 56*32; i += 256) {
        int r = i >> 5, q = i & 31;
        float4 v = *(const float4*)&xp[(size_t)r*CCH + q*4];
        v.x = to_tf32(v.x); v.y = to_tf32(v.y); v.z = to_tf32(v.z); v.w = to_tf32(v.w);
        *(float4*)&X[r*132 + q*4] = v;
    }
    __syncthreads();

    int wid = t >> 5, lane = t & 31, g = lane >> 2, tig = lane & 3;
    int warpM = wid & 1, warpN = wid >> 1;   // 2 x 4
    float cr[4][4], ci[4][4];
    #pragma unroll
    for (int nt=0;nt<4;nt++)
        #pragma unroll
        for (int j=0;j<4;j++){ cr[nt][j]=0.f; ci[nt][j]=0.f; }

    #pragma unroll
    for (int ks = 0; ks < 7; ks++) {
        int row = warpM*16 + g, col = ks*8 + tig;
        uint32_t aC[4], aS[4];
        aC[0]=__float_as_uint(Cs[row*68+col]);     aC[1]=__float_as_uint(Cs[(row+8)*68+col]);
        aC[2]=__float_as_uint(Cs[row*68+col+4]);   aC[3]=__float_as_uint(Cs[(row+8)*68+col+4]);
        aS[0]=__float_as_uint(Ss[row*68+col]);     aS[1]=__float_as_uint(Ss[(row+8)*68+col]);
        aS[2]=__float_as_uint(Ss[row*68+col+4]);   aS[3]=__float_as_uint(Ss[(row+8)*68+col+4]);
        #pragma unroll
        for (int nt = 0; nt < 4; nt++) {
            int n = warpN*32 + nt*8 + g;
            uint32_t b0 = __float_as_uint(X[(ks*8+tig)*132 + n]);
            uint32_t b1 = __float_as_uint(X[(ks*8+tig+4)*132 + n]);
            mma1688(cr[nt], aC, b0, b1);
            mma1688(ci[nt], aS, b0, b1);
        }
    }

    size_t ob = (size_t)bh*WF*CCH + c0;
    #pragma unroll
    for (int nt = 0; nt < 4; nt++) {
        int n2 = warpN*32 + nt*8 + 2*tig;
        int k0r = warpM*16 + g, k1r = k0r + 8;
        *(float2*)&g_Ar[ob + (size_t)k0r*CCH + n2] = make_float2(cr[nt][0], cr[nt][1]);
        *(float2*)&g_Ai[ob + (size_t)k0r*CCH + n2] = make_float2(ci[nt][0], ci[nt][1]);
        if (k1r < WF) {
            *(float2*)&g_Ar[ob + (size_t)k1r*CCH + n2] = make_float2(cr[nt][2], cr[nt][3]);
            *(float2*)&g_Ai[ob + (size_t)k1r*CCH + n2] = make_float2(ci[nt][2], ci[nt][3]);
        }
    }
}

// ================= stage 2/5: complex FFT along H (K=56, 7 ks) ===============
#define FH_C  0
#define FH_S  (64*68)
#define FH_XR (2*64*68)
#define FH_XI (2*64*68 + 64*132)
#define FH_TOT ((2*64*68 + 2*64*132)*4)
#define HROW (WF*CCH)   // 22272

template<int DIR>
__global__ void __launch_bounds__(256, 2) fftHT_k()
{
    extern __shared__ float sm[];
    float* Cs = sm + FH_C;
    float* Ss = sm + FH_S;
    float* XR = sm + FH_XR;
    float* XI = sm + FH_XI;
    int b  = blockIdx.x;
    int j0 = blockIdx.y * 128;
    int t  = threadIdx.x;

    const float* inR  = (DIR==0) ? g_Ar : g_Br;
    const float* inI  = (DIR==0) ? g_Ai : g_Bi;
    float*       outR = (DIR==0) ? g_Br : g_Ar;
    float*       outI = (DIR==0) ? g_Bi : g_Ai;

    for (int i = t; i < 64*64; i += 256) {
        int r = i >> 6, c = i & 63;
        Cs[r*68+c] = g_Ch[i];
        float s = g_Sh[i];
        Ss[r*68+c] = (DIR==0) ? s : -s;
    }
    size_t base = (size_t)b*HH*HROW + j0;
    for (int i = t; i < 56*32; i += 256) {
        int r = i >> 5, q = i & 31;
        float4 vr = *(const float4*)&inR[base + (size_t)r*HROW + q*4];
        float4 vi = *(const float4*)&inI[base + (size_t)r*HROW + q*4];
        vr.x=to_tf32(vr.x); vr.y=to_tf32(vr.y); vr.z=to_tf32(vr.z); vr.w=to_tf32(vr.w);
        vi.x=to_tf32(vi.x); vi.y=to_tf32(vi.y); vi.z=to_tf32(vi.z); vi.w=to_tf32(vi.w);
        *(float4*)&XR[r*132 + q*4] = vr;
        *(float4*)&XI[r*132 + q*4] = vi;
    }
    __syncthreads();

    int wid = t >> 5, lane = t & 31, g = lane >> 2, tig = lane & 3;
    int warpM = wid & 3, warpN = wid >> 2;   // 4 x 2
    float cr[8][4], ci[8][4];
    #pragma unroll
    for (int nt=0;nt<8;nt++)
        #pragma unroll
        for (int j=0;j<4;j++){ cr[nt][j]=0.f; ci[nt][j]=0.f; }

    #pragma unroll
    for (int ks = 0; ks < 7; ks++) {
        int row = warpM*16 + g, col = ks*8 + tig;
        uint32_t aC[4], aS[4], aSn[4];
        aC[0]=__float_as_uint(Cs[row*68+col]);     aC[1]=__float_as_uint(Cs[(row+8)*68+col]);
        aC[2]=__float_as_uint(Cs[row*68+col+4]);   aC[3]=__float_as_uint(Cs[(row+8)*68+col+4]);
        aS[0]=__float_as_uint(Ss[row*68+col]);     aS[1]=__float_as_uint(Ss[(row+8)*68+col]);
        aS[2]=__float_as_uint(Ss[row*68+col+4]);   aS[3]=__float_as_uint(Ss[(row+8)*68+col+4]);
        #pragma unroll
        for (int j=0;j<4;j++) aSn[j] = aS[j] ^ 0x80000000u;
        #pragma unroll
        for (int nt = 0; nt < 8; nt++) {
            int n = warpN*64 + nt*8 + g;
            uint32_t br0 = __float_as_uint(XR[(ks*8+tig)*132 + n]);
            uint32_t br1 = __float_as_uint(XR[(ks*8+tig+4)*132 + n]);
            uint32_t bi0 = __float_as_uint(XI[(ks*8+tig)*132 + n]);
            uint32_t bi1 = __float_as_uint(XI[(ks*8+tig+4)*132 + n]);
            mma1688(cr[nt], aC,  br0, br1);
            mma1688(cr[nt], aS,  bi0, bi1);
            mma1688(ci[nt], aC,  bi0, bi1);
            mma1688(ci[nt], aSn, br0, br1);
        }
    }

    int k0r = warpM*16 + g;
    #pragma unroll
    for (int nt = 0; nt < 8; nt++) {
        int n2 = warpN*64 + nt*8 + 2*tig;
        float2 r0 = make_float2(cr[nt][0], cr[nt][1]);
        float2 i0 = make_float2(ci[nt][0], ci[nt][1]);
        float2 r1 = make_float2(cr[nt][2], cr[nt][3]);
        float2 i1 = make_float2(ci[nt][2], ci[nt][3]);
        if (DIR == 0) {   // feeds cp.async GEMM: pre-round
            r0.x=to_tf32(r0.x); r0.y=to_tf32(r0.y); i0.x=to_tf32(i0.x); i0.y=to_tf32(i0.y);
            r1.x=to_tf32(r1.x); r1.y=to_tf32(r1.y); i1.x=to_tf32(i1.x); i1.y=to_tf32(i1.y);
        }
        *(float2*)&outR[base + (size_t)k0r*HROW + n2] = r0;
        *(float2*)&outI[base + (size_t)k0r*HROW + n2] = i0;
        if (warpM < 3) {
            *(float2*)&outR[base + (size_t)(k0r+8)*HROW + n2] = r1;
            *(float2*)&outI[base + (size_t)(k0r+8)*HROW + n2] = i1;
        }
    }
}

// ================= stage 6: inverse rfft along W via tensor mma ==============
#define IW_C  0
#define IW_S  (64*36)
#define IW_XR (2*64*36)
#define IW_XI (2*64*36 + 32*132)
#define IW_TOT ((2*64*36 + 2*32*132)*4)

__global__ void __launch_bounds__(256, 2) irfftWT_k(float* __restrict__ out)
{
    extern __shared__ float sm[];
    float* Cs = sm + IW_C;
    float* Ss = sm + IW_S;
    float* XR = sm + IW_XR;
    float* XI = sm + IW_XI;
    int bh = blockIdx.x;
    int c0 = blockIdx.y * 128;
    int t  = threadIdx.x;

    for (int i = t; i < 64*32; i += 256) {
        int r = i >> 5, c = i & 31;
        Cs[r*36+c] = g_Cw2[i]; Ss[r*36+c] = g_Sw2n[i];
    }
    size_t base = (size_t)bh*WF*CCH + c0;
    for (int i = t; i < 32*32; i += 256) {
        int r = i >> 5, q = i & 31;
        float4 vr = make_float4(0.f,0.f,0.f,0.f), vi = vr;
        if (r < WF) {
            vr = *(const float4*)&g_Ar[base + (size_t)r*CCH + q*4];
            vi = *(const float4*)&g_Ai[base + (size_t)r*CCH + q*4];
        }
        vr.x=to_tf32(vr.x); vr.y=to_tf32(vr.y); vr.z=to_tf32(vr.z); vr.w=to_tf32(vr.w);
        vi.x=to_tf32(vi.x); vi.y=to_tf32(vi.y); vi.z=to_tf32(vi.z); vi.w=to_tf32(vi.w);
        *(float4*)&XR[r*132 + q*4] = vr;
        *(float4*)&XI[r*132 + q*4] = vi;
    }
    __syncthreads();

    int wid = t >> 5, lane = t & 31, g = lane >> 2, tig = lane & 3;
    int warpM = wid & 3, warpN = wid >> 2;   // 4 x 2
    float co[8][4];
    #pragma unroll
    for (int nt=0;nt<8;nt++)
        #pragma unroll
        for (int j=0;j<4;j++) co[nt][j]=0.f;

    #pragma unroll
    for (int ks = 0; ks < 4; ks++) {
        int row = warpM*16 + g, col = ks*8 + tig;
        uint32_t aC[4], aS[4];
        aC[0]=__float_as_uint(Cs[row*36+col]);     aC[1]=__float_as_uint(Cs[(row+8)*36+col]);
        aC[2]=__float_as_uint(Cs[row*36+col+4]);   aC[3]=__float_as_uint(Cs[(row+8)*36+col+4]);
        aS[0]=__float_as_uint(Ss[row*36+col]);     aS[1]=__float_as_uint(Ss[(row+8)*36+col]);
        aS[2]=__float_as_uint(Ss[row*36+col+4]);   aS[3]=__float_as_uint(Ss[(row+8)*36+col+4]);
        #pragma unroll
        for (int nt = 0; nt < 8; nt++) {
            int n = warpN*64 + nt*8 + g;
            uint32_t br0 = __float_as_uint(XR[(ks*8+tig)*132 + n]);
            uint32_t br1 = __float_as_uint(XR[(ks*8+tig+4)*132 + n]);
            uint32_t bi0 = __float_as_uint(XI[(ks*8+tig)*132 + n]);
            uint32_t bi1 = __float_as_uint(XI[(ks*8+tig+4)*132 + n]);
            mma1688(co[nt], aC, br0, br1);
            mma1688(co[nt], aS, bi0, bi1);
        }
    }

    int w0 = warpM*16 + g;
    size_t ob = (size_t)bh*WW*CCH + c0;
    #pragma unroll
    for (int nt = 0; nt < 8; nt++) {
        int n2 = warpN*64 + nt*8 + 2*tig;
        *(float2*)&out[ob + (size_t)w0*CCH + n2] = make_float2(co[nt][0], co[nt][1]);
        if (warpM < 3)
            *(float2*)&out[ob + (size_t)(w0+8)*CCH + n2] = make_float2(co[nt][2], co[nt][3]);
    }
}

// ========== MLP GEMM: R6 config — 128x128, 256 thr, 2 CTA/SM, 3-stage ========
#define GA0 0
#define GA1 4608
#define GA2 9216
#define GB0 13824
#define GB1 18432
#define GB2 23040
#define GBIAS 27648
#define GEMM_SMEM ((27648 + 128)*4)   // 111104 B (2 CTAs/SM)

template<int LAYER>
__device__ __forceinline__ void gload(int blk, int p0, int n0, int kc,
                                      uint32_t aS, uint32_t bS, int t)
{
    const float* inR = (LAYER==1) ? g_Br : g_Ar;
    const float* inI = (LAYER==1) ? g_Bi : g_Ai;
    const float* Wt  = ((LAYER==1) ? g_W1 : g_W2) + (size_t)blk*384*384;
    const float* src = (kc < 6) ? inR : inI;
    int koff = blk*192 + ((kc < 6) ? kc*32 : (kc-6)*32);
    int row = t >> 3, q = t & 7;
    #pragma unroll
    for (int i = 0; i < 4; i++) {
        int r = row + i*32;
        CP_ASYNC16(aS + (uint32_t)(r*36 + q*4)*4, &src[(size_t)(p0+r)*CCH + koff + q*4]);
    }
    int kb = kc*32;
    #pragma unroll
    for (int i = 0; i < 4; i++) {
        int r = row + i*32;
        CP_ASYNC16(bS + (uint32_t)(r*36 + q*4)*4, &Wt[(size_t)(n0+r)*384 + kb + q*4]);
    }
}

__device__ __forceinline__ void gcompute(const float* __restrict__ As,
                                         const float* __restrict__ Bs,
                                         float c[2][8][4],
                                         int warpM, int warpN, int g, int tig)
{
    #pragma unroll
    for (int ks = 0; ks < 4; ks++) {
        uint32_t a[2][4];
        #pragma unroll
        for (int mt = 0; mt < 2; mt++) {
            int r = warpM*32 + mt*16 + g;
            int col = ks*8 + tig;
            a[mt][0] = __float_as_uint(As[r*36 + col]);
            a[mt][1] = __float_as_uint(As[(r+8)*36 + col]);
            a[mt][2] = __float_as_uint(As[r*36 + col + 4]);
            a[mt][3] = __float_as_uint(As[(r+8)*36 + col + 4]);
        }
        #pragma unroll
        for (int nt = 0; nt < 8; nt++) {
            int n = warpN*64 + nt*8 + g;
            uint32_t b0 = __float_as_uint(Bs[n*36 + ks*8 + tig]);
            uint32_t b1 = __float_as_uint(Bs[n*36 + ks*8 + tig + 4]);
            mma1688(c[0][nt], a[0], b0, b1);
            mma1688(c[1][nt], a[1], b0, b1);
        }
    }
}

template<int LAYER>
__global__ void __launch_bounds__(256, 2) gemmM_k()
{
    extern __shared__ float sm[];
    uint32_t smem_base = smem_u32(sm);
    int t = threadIdx.x;
    int wid = t >> 5, lane = t & 31;
    int g = lane >> 2, tig = lane & 3;
    int warpM = wid & 3, warpN = wid >> 2;
    int p0  = blockIdx.x * 128;
    int n0  = blockIdx.y * 128;
    int blk = blockIdx.z;

    float*       outR = (LAYER==1) ? g_Ar : g_Br;
    float*       outI = (LAYER==1) ? g_Ai : g_Bi;
    const float* bias = ((LAYER==1) ? g_b1 : g_b2) + blk*384;

    for (int i = t; i < 128; i += 256) sm[GBIAS + i] = bias[n0 + i];

    float c[2][8][4];
    #pragma unroll
    for (int mt=0;mt<2;mt++)
        #pragma unroll
        for (int nt=0;nt<8;nt++)
            #pragma unroll
            for (int j=0;j<4;j++) c[mt][nt][j] = 0.f;

    gload<LAYER>(blk, p0, n0, 0, smem_base + GA0*4, smem_base + GB0*4, t);
    CP_COMMIT();
    gload<LAYER>(blk, p0, n0, 1, smem_base + GA1*4, smem_base + GB1*4, t);
    CP_COMMIT();

    #define GEMM_STEP(KC, AOFF, BOFF, NA, NB, DO_LOAD, LAST)                    \
        do {                                                                    \
            if (LAST) { CP_WAIT(0); } else { CP_WAIT(1); }                      \
            __syncthreads();                                                    \
            if (DO_LOAD) {                                                      \
                gload<LAYER>(blk, p0, n0, (KC)+2,                               \
                             smem_base + (NA)*4, smem_base + (NB)*4, t);        \
                CP_COMMIT();                                                    \
            }                                                                   \
            gcompute(sm + (AOFF), sm + (BOFF), c, warpM, warpN, g, tig);        \
        } while (0)

    #pragma unroll 1
    for (int kq = 0; kq < 4; kq++) {
        int kc0 = kq*3;
        GEMM_STEP(kc0+0, GA0, GB0, GA2, GB2, true,     false);
        GEMM_STEP(kc0+1, GA1, GB1, GA0, GB0, (kq < 3), false);
        GEMM_STEP(kc0+2, GA2, GB2, GA1, GB1, (kq < 3), (kq == 3));
    }
    #undef GEMM_STEP

    #pragma unroll
    for (int mt = 0; mt < 2; mt++) {
        #pragma unroll
        for (int rr = 0; rr < 2; rr++) {
            int r = p0 + warpM*32 + mt*16 + rr*8 + g;
            size_t rowoff = (size_t)r*CCH + blk*192;
            #pragma unroll
            for (int nt = 0; nt < 8; nt++) {
                int kl = warpN*64 + nt*8 + 2*tig;
                int ko = n0 + kl;
                float v0 = c[mt][nt][rr*2+0] + sm[GBIAS + kl];
                float v1 = c[mt][nt][rr*2+1] + sm[GBIAS + kl + 1];
                if (LAYER == 1) {
                    v0 = to_tf32(fmaxf(v0, 0.f));
                    v1 = to_tf32(fmaxf(v1, 0.f));
                } else {
                    v0 = (v0 >  SSHRINK) ? v0-SSHRINK : ((v0 < -SSHRINK) ? v0+SSHRINK : 0.f);
                    v1 = (v1 >  SSHRINK) ? v1-SSHRINK : ((v1 < -SSHRINK) ? v1+SSHRINK : 0.f);
                }
                float* dst = (ko < 192) ? outR : outI;
                int kr = (ko < 192) ? ko : ko - 192;
                *(float2*)&dst[rowoff + kr] = make_float2(v0, v1);
            }
        }
    }
}

// ---------------- launch ------------------------------------------------------
extern "C" void kernel_launch(void* const* d_in, const int* in_sizes, int n_in,
                              void* d_out, int out_size)
{
    const float* x  = (const float*)d_in[0];
    const float* w1 = (const float*)d_in[1];
    const float* b1 = (const float*)d_in[2];
    const float* w2 = (const float*)d_in[3];
    const float* b2 = (const float*)d_in[4];
    float* out = (float*)d_out;

    cudaFuncSetAttribute((const void*)rfftWT_k,   cudaFuncAttributeMaxDynamicSharedMemorySize, RW_TOT);
    cudaFuncSetAttribute((const void*)fftHT_k<0>, cudaFuncAttributeMaxDynamicSharedMemorySize, FH_TOT);
    cudaFuncSetAttribute((const void*)fftHT_k<1>, cudaFuncAttributeMaxDynamicSharedMemorySize, FH_TOT);
    cudaFuncSetAttribute((const void*)irfftWT_k,  cudaFuncAttributeMaxDynamicSharedMemorySize, IW_TOT);
    cudaFuncSetAttribute((const void*)gemmM_k<1>, cudaFuncAttributeMaxDynamicSharedMemorySize, GEMM_SMEM);
    cudaFuncSetAttribute((const void*)gemmM_k<2>, cudaFuncAttributeMaxDynamicSharedMemorySize, GEMM_SMEM);

    init_k<<<512, 256>>>(w1, b1, w2, b2);
    rfftWT_k<<<dim3(BB*HH, 6), 256, RW_TOT>>>(x);
    fftHT_k<0><<<dim3(BB, 174), 256, FH_TOT>>>();
    gemmM_k<1><<<dim3(406, 3, NBLK), 256, GEMM_SMEM>>>();
    gemmM_k<2><<<dim3(406, 3, NBLK), 256, GEMM_SMEM>>>();
    fftHT_k<1><<<dim3(BB, 174), 256, FH_TOT>>>();
    irfftWT_k<<<dim3(BB*HH, 6), 256, IW_TOT>>>(out);
}

// round 11
// speedup vs baseline: 1.3212x; 1.2402x over previous
#include <cuda_runtime.h>
#include <cstdint>

#define HH 56
#define WW 56
#define WF 29          // 56/2 + 1
#define BB 32
#define CCH 768
#define NBLK 4
#define SPEC (BB*HH*WF*CCH)
#define SSHRINK 0.01f

typedef unsigned long long ull;

// ---------------- scratch (device globals; no allocation allowed) -------------
__device__ float g_Ar[SPEC];
__device__ float g_Ai[SPEC];
__device__ float g_Br[SPEC];
__device__ float g_Bi[SPEC];

// tf32 DFT matrices (padded to mma tiles, pads = 0)
__device__ float g_Ch[64*64],  g_Sh[64*64];    // H-FFT: [k][h], k,h<56
__device__ float g_Cwf[32*64], g_Swfn[32*64];  // fwd rfft W: [kf][w] (Swfn = -sin)
__device__ float g_Cw2[64*32], g_Sw2n[64*32];  // inv rfft W: [w][k] (1/2/1, Sw2n=-a*sin)

// TRANSPOSED expanded weights (B[n][k] = W[k][n]), tf32-rounded: [blk][384][384]
__device__ float g_W1[NBLK*384*384], g_W2[NBLK*384*384];
__device__ float g_b1[NBLK*384],     g_b2[NBLK*384];

__device__ __forceinline__ float to_tf32(float x){
    uint32_t u; asm("cvt.rna.tf32.f32 %0, %1;" : "=r"(u) : "f"(x));
    return __uint_as_float(u);
}
__device__ __forceinline__ uint32_t smem_u32(const void* p) {
    uint32_t a;
    asm("{ .reg .u64 t; cvta.to.shared.u64 t, %1; cvt.u32.u64 %0, t; }" : "=r"(a) : "l"(p));
    return a;
}
#define CP_ASYNC16(sa, gp) \
    asm volatile("cp.async.cg.shared.global [%0], [%1], 16;" :: "r"(sa), "l"(gp))
#define CP_COMMIT() asm volatile("cp.async.commit_group;" ::: "memory")
#define CP_WAIT(n)  asm volatile("cp.async.wait_group %0;" :: "n"(n) : "memory")

__device__ __forceinline__ void mma1688(float c[4], const uint32_t a[4], uint32_t b0, uint32_t b1){
    asm volatile("mma.sync.aligned.m16n8k8.row.col.f32.tf32.tf32.f32 "
        "{%0,%1,%2,%3}, {%4,%5,%6,%7}, {%8,%9}, {%0,%1,%2,%3};"
        : "+f"(c[0]), "+f"(c[1]), "+f"(c[2]), "+f"(c[3])
        : "r"(a[0]), "r"(a[1]), "r"(a[2]), "r"(a[3]), "r"(b0), "r"(b1));
}

// ---------------- init: tf32 DFT matrices + transposed tf32 weights ----------
__global__ void init_k(const float* __restrict__ w1, const float* __restrict__ b1,
                       const float* __restrict__ w2, const float* __restrict__ b2)
{
    int tid = blockIdx.x*blockDim.x + threadIdx.x;
    int nt  = gridDim.x*blockDim.x;
    const double TW  = 6.283185307179586476925286766559 / 56.0;
    const double INV = 0.13363062095621219234827870598923; // 1/sqrt(56)

    for (int i = tid; i < 64*64; i += nt) {
        int k = i >> 6, h = i & 63;
        float c = 0.f, s = 0.f;
        if (k < 56 && h < 56) {
            int m = (k*h) % 56;
            c = to_tf32((float)(cos(TW*m)*INV));
            s = to_tf32((float)(sin(TW*m)*INV));
        }
        g_Ch[i] = c; g_Sh[i] = s;
    }
    for (int i = tid; i < 32*64; i += nt) {
        int kf = i >> 6, w = i & 63;
        float c = 0.f, s = 0.f;
        if (kf < WF && w < 56) {
            int m = (kf*w) % 56;
            c = to_tf32((float)(cos(TW*m)*INV));
            s = to_tf32((float)(-sin(TW*m)*INV));
        }
        g_Cwf[i] = c; g_Swfn[i] = s;
    }
    for (int i = tid; i < 64*32; i += nt) {
        int w = i >> 5, k = i & 31;
        float c = 0.f, s = 0.f;
        if (w < 56 && k < WF) {
            int m = (k*w) % 56;
            double a = (k==0 || k==WF-1) ? 1.0 : 2.0;
            c = to_tf32((float)(a*cos(TW*m)*INV));
            s = to_tf32((float)(-a*sin(TW*m)*INV));
        }
        g_Cw2[i] = c; g_Sw2n[i] = s;
    }
    for (int i = tid; i < NBLK*384*384; i += nt) {
        int blk = i / (384*384);
        int n   = (i / 384) % 384;
        int kd  = i % 384;
        int r = kd, k = n;
        int d  = (r < 192) ? r : r-192;
        int kk = (k < 192) ? k : k-192;
        float v1, v2;
        if (r < 192) {
            if (k < 192) { v1 =  w1[((0*NBLK+blk)*192+d)*192+kk]; v2 =  w2[((0*NBLK+blk)*192+d)*192+kk]; }
            else         { v1 =  w1[((1*NBLK+blk)*192+d)*192+kk]; v2 =  w2[((1*NBLK+blk)*192+d)*192+kk]; }
        } else {
            if (k < 192) { v1 = -w1[((1*NBLK+blk)*192+d)*192+kk]; v2 = -w2[((1*NBLK+blk)*192+d)*192+kk]; }
            else         { v1 =  w1[((0*NBLK+blk)*192+d)*192+kk]; v2 =  w2[((0*NBLK+blk)*192+d)*192+kk]; }
        }
        g_W1[i] = to_tf32(v1); g_W2[i] = to_tf32(v2);
    }
    for (int i = tid; i < NBLK*384; i += nt) {
        int blk = i / 384, k = i % 384;
        g_b1[i] = (k < 192) ? b1[(0*NBLK+blk)*192 + k] : b1[(1*NBLK+blk)*192 + k-192];
        g_b2[i] = (k < 192) ? b2[(0*NBLK+blk)*192 + k] : b2[(1*NBLK+blk)*192 + k-192];
    }
}

// ========== stage 1: rfft along W — cp.async pipelined, 64-wide chunks =======
#define RW_C   0
#define RW_S   (32*68)
#define RW_X0  (2*32*68)            // 4352
#define RW_BUF (56*72)              // 4032
#define RW_TOT ((2*32*68 + 2*56*72)*4)   // 49664 B -> 4 CTAs/SM

__device__ __forceinline__ void rw_load(uint32_t bS, const float* __restrict__ xb,
                                        int c0, int t)
{
    #pragma unroll
    for (int i = 0; i < 4; i++) {
        int idx = t + i*256;
        if (idx < 896) {                       // 56 rows x 16 quads
            int row = idx >> 4, q = idx & 15;
            CP_ASYNC16(bS + (uint32_t)(row*72 + q*4)*4,
                       &xb[(size_t)row*CCH + c0 + q*4]);
        }
    }
    CP_COMMIT();
}

__global__ void __launch_bounds__(256, 4) rfftWT_k(const float* __restrict__ x)
{
    extern __shared__ float sm[];
    uint32_t smem_base = smem_u32(sm);
    float* Cs = sm + RW_C;
    float* Ss = sm + RW_S;
    int bh = blockIdx.x;
    int t  = threadIdx.x;

    for (int i = t; i < 32*64; i += 256) {
        int r = i >> 6, c = i & 63;
        Cs[r*68+c] = g_Cwf[i]; Ss[r*68+c] = g_Swfn[i];
    }

    const float* xb = x + (size_t)bh*WW*CCH;
    int cbase = blockIdx.y * 4 * 64;

    rw_load(smem_base + (RW_X0 + 0*RW_BUF)*4, xb, cbase,      t);
    rw_load(smem_base + (RW_X0 + 1*RW_BUF)*4, xb, cbase + 64, t);

    int wid = t >> 5, lane = t & 31, g = lane >> 2, tig = lane & 3;
    int warpM = wid & 1, warpN = wid >> 1;   // 2 x 4 (N-tile 16)

    #pragma unroll 1
    for (int c = 0; c < 4; c++) {
        if (c == 3) { CP_WAIT(0); } else { CP_WAIT(1); }
        __syncthreads();
        const float* X = sm + RW_X0 + (c & 1)*RW_BUF;
        int c0 = cbase + c*64;

        float cr[2][4], ci[2][4];
        #pragma unroll
        for (int nt=0;nt<2;nt++)
            #pragma unroll
            for (int j=0;j<4;j++){ cr[nt][j]=0.f; ci[nt][j]=0.f; }

        #pragma unroll
        for (int ks = 0; ks < 7; ks++) {
            int row = warpM*16 + g, col = ks*8 + tig;
            uint32_t aC[4], aS[4];
            aC[0]=__float_as_uint(Cs[row*68+col]);     aC[1]=__float_as_uint(Cs[(row+8)*68+col]);
            aC[2]=__float_as_uint(Cs[row*68+col+4]);   aC[3]=__float_as_uint(Cs[(row+8)*68+col+4]);
            aS[0]=__float_as_uint(Ss[row*68+col]);     aS[1]=__float_as_uint(Ss[(row+8)*68+col]);
            aS[2]=__float_as_uint(Ss[row*68+col+4]);   aS[3]=__float_as_uint(Ss[(row+8)*68+col+4]);
            #pragma unroll
            for (int nt = 0; nt < 2; nt++) {
                int n = warpN*16 + nt*8 + g;
                uint32_t b0 = __float_as_uint(to_tf32(X[(ks*8+tig)*72 + n]));
                uint32_t b1 = __float_as_uint(to_tf32(X[(ks*8+tig+4)*72 + n]));
                mma1688(cr[nt], aC, b0, b1);
                mma1688(ci[nt], aS, b0, b1);
            }
        }

        size_t ob = (size_t)bh*WF*CCH + c0;
        #pragma unroll
        for (int nt = 0; nt < 2; nt++) {
            int n2 = warpN*16 + nt*8 + 2*tig;
            int k0r = warpM*16 + g, k1r = k0r + 8;
            float2 r0 = make_float2(to_tf32(cr[nt][0]), to_tf32(cr[nt][1]));
            float2 i0 = make_float2(to_tf32(ci[nt][0]), to_tf32(ci[nt][1]));
            *(float2*)&g_Ar[ob + (size_t)k0r*CCH + n2] = r0;
            *(float2*)&g_Ai[ob + (size_t)k0r*CCH + n2] = i0;
            if (k1r < WF) {
                float2 r1 = make_float2(to_tf32(cr[nt][2]), to_tf32(cr[nt][3]));
                float2 i1 = make_float2(to_tf32(ci[nt][2]), to_tf32(ci[nt][3]));
                *(float2*)&g_Ar[ob + (size_t)k1r*CCH + n2] = r1;
                *(float2*)&g_Ai[ob + (size_t)k1r*CCH + n2] = i1;
            }
        }

        if (c + 2 < 4) {
            __syncthreads();
            rw_load(smem_base + (RW_X0 + (c & 1)*RW_BUF)*4, xb, c0 + 128, t);
        }
    }
}

// ========== stage 2/5: complex FFT along H — cp.async pipelined ==============
#define FH_C   0
#define FH_S   (64*68)
#define FH_B0  (2*64*68)            // 8704
#define FH_XI_OFF (56*72)           // 4032 within buffer
#define FH_BUF (2*56*72)            // 8064
#define FH_TOT ((2*64*68 + 2*2*56*72)*4)   // 99328 B -> 2 CTAs/SM
#define HROW (WF*CCH)   // 22272

__device__ __forceinline__ void fh_load(uint32_t bS,
                                        const float* __restrict__ inR,
                                        const float* __restrict__ inI,
                                        size_t gb, int t)
{
    #pragma unroll
    for (int i = 0; i < 7; i++) {          // 2 arrays x 56 rows x 16 quads = 1792 = 7*256
        int idx = t + i*256;
        int a = (idx >= 896) ? 1 : 0;
        int rem = idx - a*896;
        int row = rem >> 4, q = rem & 15;
        const float* src = a ? inI : inR;
        CP_ASYNC16(bS + (uint32_t)(a*FH_XI_OFF + row*72 + q*4)*4,
                   &src[gb + (size_t)row*HROW + q*4]);
    }
    CP_COMMIT();
}

template<int DIR>
__global__ void __launch_bounds__(256, 2) fftHT_k()
{
    extern __shared__ float sm[];
    uint32_t smem_base = smem_u32(sm);
    float* Cs = sm + FH_C;
    float* Ss = sm + FH_S;
    int b  = blockIdx.x;
    int t  = threadIdx.x;

    const float* inR  = (DIR==0) ? g_Ar : g_Br;
    const float* inI  = (DIR==0) ? g_Ai : g_Bi;
    float*       outR = (DIR==0) ? g_Br : g_Ar;
    float*       outI = (DIR==0) ? g_Bi : g_Ai;

    for (int i = t; i < 64*64; i += 256) {
        int r = i >> 6, c = i & 63;
        Cs[r*68+c] = g_Ch[i];
        float s = g_Sh[i];
        Ss[r*68+c] = (DIR==0) ? s : -s;
    }

    size_t bbase = (size_t)b*HH*HROW;
    int jbase = blockIdx.y * 6 * 64;   // T=6

    fh_load(smem_base + (FH_B0 + 0*FH_BUF)*4, inR, inI, bbase + jbase,      t);
    fh_load(smem_base + (FH_B0 + 1*FH_BUF)*4, inR, inI, bbase + jbase + 64, t);

    int wid = t >> 5, lane = t & 31, g = lane >> 2, tig = lane & 3;
    int warpM = wid & 3, warpN = wid >> 2;   // 4 x 2 (N-tile 32)

    #pragma unroll 1
    for (int c = 0; c < 6; c++) {
        if (c == 5) { CP_WAIT(0); } else { CP_WAIT(1); }
        __syncthreads();
        const float* XR = sm + FH_B0 + (c & 1)*FH_BUF;
        const float* XI = XR + FH_XI_OFF;
        int j0 = jbase + c*64;
        size_t base = bbase + j0;

        float cr[4][4], ci[4][4];
        #pragma unroll
        for (int nt=0;nt<4;nt++)
            #pragma unroll
            for (int j=0;j<4;j++){ cr[nt][j]=0.f; ci[nt][j]=0.f; }

        #pragma unroll
        for (int ks = 0; ks < 7; ks++) {
            int row = warpM*16 + g, col = ks*8 + tig;
            uint32_t aC[4], aS[4], aSn[4];
            aC[0]=__float_as_uint(Cs[row*68+col]);     aC[1]=__float_as_uint(Cs[(row+8)*68+col]);
            aC[2]=__float_as_uint(Cs[row*68+col+4]);   aC[3]=__float_as_uint(Cs[(row+8)*68+col+4]);
            aS[0]=__float_as_uint(Ss[row*68+col]);     aS[1]=__float_as_uint(Ss[(row+8)*68+col]);
            aS[2]=__float_as_uint(Ss[row*68+col+4]);   aS[3]=__float_as_uint(Ss[(row+8)*68+col+4]);
            #pragma unroll
            for (int j=0;j<4;j++) aSn[j] = aS[j] ^ 0x80000000u;
            #pragma unroll
            for (int nt = 0; nt < 4; nt++) {
                int n = warpN*32 + nt*8 + g;
                uint32_t br0 = __float_as_uint(XR[(ks*8+tig)*72 + n]);
                uint32_t br1 = __float_as_uint(XR[(ks*8+tig+4)*72 + n]);
                uint32_t bi0 = __float_as_uint(XI[(ks*8+tig)*72 + n]);
                uint32_t bi1 = __float_as_uint(XI[(ks*8+tig+4)*72 + n]);
                mma1688(cr[nt], aC,  br0, br1);
                mma1688(cr[nt], aS,  bi0, bi1);
                mma1688(ci[nt], aC,  bi0, bi1);
                mma1688(ci[nt], aSn, br0, br1);
            }
        }

        int k0r = warpM*16 + g;
        #pragma unroll
        for (int nt = 0; nt < 4; nt++) {
            int n2 = warpN*32 + nt*8 + 2*tig;
            float2 r0 = make_float2(to_tf32(cr[nt][0]), to_tf32(cr[nt][1]));
            float2 i0 = make_float2(to_tf32(ci[nt][0]), to_tf32(ci[nt][1]));
            *(float2*)&outR[base + (size_t)k0r*HROW + n2] = r0;
            *(float2*)&outI[base + (size_t)k0r*HROW + n2] = i0;
            if (warpM < 3) {
                float2 r1 = make_float2(to_tf32(cr[nt][2]), to_tf32(cr[nt][3]));
                float2 i1 = make_float2(to_tf32(ci[nt][2]), to_tf32(ci[nt][3]));
                *(float2*)&outR[base + (size_t)(k0r+8)*HROW + n2] = r1;
                *(float2*)&outI[base + (size_t)(k0r+8)*HROW + n2] = i1;
            }
        }

        if (c + 2 < 6) {
            __syncthreads();
            fh_load(smem_base + (FH_B0 + (c & 1)*FH_BUF)*4, inR, inI,
                    bbase + j0 + 128, t);
        }
    }
}

// ========== stage 6: inverse rfft along W — cp.async pipelined ===============
#define IW_C   0
#define IW_S   (64*36)
#define IW_B0  (2*64*36)           // 4608
#define IW_XI_OFF (32*72)          // 2304 within buffer
#define IW_BUF (2*32*72)           // 4608
#define IW_TOT ((2*64*36 + 2*2*32*72)*4)   // 55296 B -> 4 CTAs/SM

__device__ __forceinline__ void iw_load(uint32_t bS, size_t gb, int t)
{
    #pragma unroll
    for (int i = 0; i < 4; i++) {          // 2 arrays x 29 rows x 16 quads = 928
        int idx = t + i*256;
        if (idx < 928) {
            int a = (idx >= 464) ? 1 : 0;
            int rem = idx - a*464;
            int row = rem >> 4, q = rem & 15;
            const float* src = a ? g_Ai : g_Ar;
            CP_ASYNC16(bS + (uint32_t)(a*IW_XI_OFF + row*72 + q*4)*4,
                       &src[gb + (size_t)row*CCH + q*4]);
        }
    }
    CP_COMMIT();
}

__global__ void __launch_bounds__(256, 4) irfftWT_k(float* __restrict__ out)
{
    extern __shared__ float sm[];
    uint32_t smem_base = smem_u32(sm);
    float* Cs = sm + IW_C;
    float* Ss = sm + IW_S;
    int bh = blockIdx.x;
    int t  = threadIdx.x;

    for (int i = t; i < 64*32; i += 256) {
        int r = i >> 5, c = i & 31;
        Cs[r*36+c] = g_Cw2[i]; Ss[r*36+c] = g_Sw2n[i];
    }
    // zero pad rows 29..31 of both arrays in both buffers (cp.async never writes them)
    for (int i = t; i < 2*2*3*72; i += 256) {
        int bu = i / (2*3*72);
        int rem = i % (2*3*72);
        int a  = rem / (3*72);
        int rr = rem % (3*72);
        sm[IW_B0 + bu*IW_BUF + a*IW_XI_OFF + (29 + rr/72)*72 + (rr%72)] = 0.f;
    }
    __syncthreads();   // pads must be visible before first compute

    size_t ibase = (size_t)bh*WF*CCH;
    int cbase = blockIdx.y * 4 * 64;

    iw_load(smem_base + (IW_B0 + 0*IW_BUF)*4, ibase + cbase,      t);
    iw_load(smem_base + (IW_B0 + 1*IW_BUF)*4, ibase + cbase + 64, t);

    int wid = t >> 5, lane = t & 31, g = lane >> 2, tig = lane & 3;
    int warpM = wid & 3, warpN = wid >> 2;   // 4 x 2 (N-tile 32)

    #pragma unroll 1
    for (int c = 0; c < 4; c++) {
        if (c == 3) { CP_WAIT(0); } else { CP_WAIT(1); }
        __syncthreads();
        const float* XR = sm + IW_B0 + (c & 1)*IW_BUF;
        const float* XI = XR + IW_XI_OFF;
        int c0 = cbase + c*64;

        float co[4][4];
        #pragma unroll
        for (int nt=0;nt<4;nt++)
            #pragma unroll
            for (int j=0;j<4;j++) co[nt][j]=0.f;

        #pragma unroll
        for (int ks = 0; ks < 4; ks++) {
            int row = warpM*16 + g, col = ks*8 + tig;
            uint32_t aC[4], aS[4];
            aC[0]=__float_as_uint(Cs[row*36+col]);     aC[1]=__float_as_uint(Cs[(row+8)*36+col]);
            aC[2]=__float_as_uint(Cs[row*36+col+4]);   aC[3]=__float_as_uint(Cs[(row+8)*36+col+4]);
            aS[0]=__float_as_uint(Ss[row*36+col]);     aS[1]=__float_as_uint(Ss[(row+8)*36+col]);
            aS[2]=__float_as_uint(Ss[row*36+col+4]);   aS[3]=__float_as_uint(Ss[(row+8)*36+col+4]);
            #pragma unroll
            for (int nt = 0; nt < 4; nt++) {
                int n = warpN*32 + nt*8 + g;
                uint32_t br0 = __float_as_uint(XR[(ks*8+tig)*72 + n]);
                uint32_t br1 = __float_as_uint(XR[(ks*8+tig+4)*72 + n]);
                uint32_t bi0 = __float_as_uint(XI[(ks*8+tig)*72 + n]);
                uint32_t bi1 = __float_as_uint(XI[(ks*8+tig+4)*72 + n]);
                mma1688(co[nt], aC, br0, br1);
                mma1688(co[nt], aS, bi0, bi1);
            }
        }

        int w0 = warpM*16 + g;
        size_t ob = (size_t)bh*WW*CCH + c0;
        #pragma unroll
        for (int nt = 0; nt < 4; nt++) {
            int n2 = warpN*32 + nt*8 + 2*tig;
            *(float2*)&out[ob + (size_t)w0*CCH + n2] = make_float2(co[nt][0], co[nt][1]);
            if (warpM < 3)
                *(float2*)&out[ob + (size_t)(w0+8)*CCH + n2] = make_float2(co[nt][2], co[nt][3]);
        }

        if (c + 2 < 4) {
            __syncthreads();
            iw_load(smem_base + (IW_B0 + (c & 1)*IW_BUF)*4, ibase + c0 + 128, t);
        }
    }
}

// ========== MLP GEMM: R6 config — 128x128, 256 thr, 2 CTA/SM, 3-stage ========
#define GA0 0
#define GA1 4608
#define GA2 9216
#define GB0 13824
#define GB1 18432
#define GB2 23040
#define GBIAS 27648
#define GEMM_SMEM ((27648 + 128)*4)   // 111104 B (2 CTAs/SM)

template<int LAYER>
__device__ __forceinline__ void gload(int blk, int p0, int n0, int kc,
                                      uint32_t aS, uint32_t bS, int t)
{
    const float* inR = (LAYER==1) ? g_Br : g_Ar;
    const float* inI = (LAYER==1) ? g_Bi : g_Ai;
    const float* Wt  = ((LAYER==1) ? g_W1 : g_W2) + (size_t)blk*384*384;
    const float* src = (kc < 6) ? inR : inI;
    int koff = blk*192 + ((kc < 6) ? kc*32 : (kc-6)*32);
    int row = t >> 3, q = t & 7;
    #pragma unroll
    for (int i = 0; i < 4; i++) {
        int r = row + i*32;
        CP_ASYNC16(aS + (uint32_t)(r*36 + q*4)*4, &src[(size_t)(p0+r)*CCH + koff + q*4]);
    }
    int kb = kc*32;
    #pragma unroll
    for (int i = 0; i < 4; i++) {
        int r = row + i*32;
        CP_ASYNC16(bS + (uint32_t)(r*36 + q*4)*4, &Wt[(size_t)(n0+r)*384 + kb + q*4]);
    }
}

__device__ __forceinline__ void gcompute(const float* __restrict__ As,
                                         const float* __restrict__ Bs,
                                         float c[2][8][4],
                                         int warpM, int warpN, int g, int tig)
{
    #pragma unroll
    for (int ks = 0; ks < 4; ks++) {
        uint32_t a[2][4];
        #pragma unroll
        for (int mt = 0; mt < 2; mt++) {
            int r = warpM*32 + mt*16 + g;
            int col = ks*8 + tig;
            a[mt][0] = __float_as_uint(As[r*36 + col]);
            a[mt][1] = __float_as_uint(As[(r+8)*36 + col]);
            a[mt][2] = __float_as_uint(As[r*36 + col + 4]);
            a[mt][3] = __float_as_uint(As[(r+8)*36 + col + 4]);
        }
        #pragma unroll
        for (int nt = 0; nt < 8; nt++) {
            int n = warpN*64 + nt*8 + g;
            uint32_t b0 = __float_as_uint(Bs[n*36 + ks*8 + tig]);
            uint32_t b1 = __float_as_uint(Bs[n*36 + ks*8 + tig + 4]);
            mma1688(c[0][nt], a[0], b0, b1);
            mma1688(c[1][nt], a[1], b0, b1);
        }
    }
}

template<int LAYER>
__global__ void __launch_bounds__(256, 2) gemmM_k()
{
    extern __shared__ float sm[];
    uint32_t smem_base = smem_u32(sm);
    int t = threadIdx.x;
    int wid = t >> 5, lane = t & 31;
    int g = lane >> 2, tig = lane & 3;
    int warpM = wid & 3, warpN = wid >> 2;
    int p0  = blockIdx.x * 128;
    int n0  = blockIdx.y * 128;
    int blk = blockIdx.z;

    float*       outR = (LAYER==1) ? g_Ar : g_Br;
    float*       outI = (LAYER==1) ? g_Ai : g_Bi;
    const float* bias = ((LAYER==1) ? g_b1 : g_b2) + blk*384;

    for (int i = t; i < 128; i += 256) sm[GBIAS + i] = bias[n0 + i];

    float c[2][8][4];
    #pragma unroll
    for (int mt=0;mt<2;mt++)
        #pragma unroll
        for (int nt=0;nt<8;nt++)
            #pragma unroll
            for (int j=0;j<4;j++) c[mt][nt][j] = 0.f;

    gload<LAYER>(blk, p0, n0, 0, smem_base + GA0*4, smem_base + GB0*4, t);
    CP_COMMIT();
    gload<LAYER>(blk, p0, n0, 1, smem_base + GA1*4, smem_base + GB1*4, t);
    CP_COMMIT();

    #define GEMM_STEP(KC, AOFF, BOFF, NA, NB, DO_LOAD, LAST)                    \
        do {                                                                    \
            if (LAST) { CP_WAIT(0); } else { CP_WAIT(1); }                      \
            __syncthreads();                                                    \
            if (DO_LOAD) {                                                      \
                gload<LAYER>(blk, p0, n0, (KC)+2,                               \
                             smem_base + (NA)*4, smem_base + (NB)*4, t);        \
                CP_COMMIT();                                                    \
            }                                                                   \
            gcompute(sm + (AOFF), sm + (BOFF), c, warpM, warpN, g, tig);        \
        } while (0)

    #pragma unroll 1
    for (int kq = 0; kq < 4; kq++) {
        int kc0 = kq*3;
        GEMM_STEP(kc0+0, GA0, GB0, GA2, GB2, true,     false);
        GEMM_STEP(kc0+1, GA1, GB1, GA0, GB0, (kq < 3), false);
        GEMM_STEP(kc0+2, GA2, GB2, GA1, GB1, (kq < 3), (kq == 3));
    }
    #undef GEMM_STEP

    #pragma unroll
    for (int mt = 0; mt < 2; mt++) {
        #pragma unroll
        for (int rr = 0; rr < 2; rr++) {
            int r = p0 + warpM*32 + mt*16 + rr*8 + g;
            size_t rowoff = (size_t)r*CCH + blk*192;
            #pragma unroll
            for (int nt = 0; nt < 8; nt++) {
                int kl = warpN*64 + nt*8 + 2*tig;
                int ko = n0 + kl;
                float v0 = c[mt][nt][rr*2+0] + sm[GBIAS + kl];
                float v1 = c[mt][nt][rr*2+1] + sm[GBIAS + kl + 1];
                if (LAYER == 1) {
                    v0 = to_tf32(fmaxf(v0, 0.f));
                    v1 = to_tf32(fmaxf(v1, 0.f));
                } else {
                    v0 = to_tf32((v0 >  SSHRINK) ? v0-SSHRINK : ((v0 < -SSHRINK) ? v0+SSHRINK : 0.f));
                    v1 = to_tf32((v1 >  SSHRINK) ? v1-SSHRINK : ((v1 < -SSHRINK) ? v1+SSHRINK : 0.f));
                }
                float* dst = (ko < 192) ? outR : outI;
                int kr = (ko < 192) ? ko : ko - 192;
                *(float2*)&dst[rowoff + kr] = make_float2(v0, v1);
            }
        }
    }
}

// ---------------- launch ------------------------------------------------------
extern "C" void kernel_launch(void* const* d_in, const int* in_sizes, int n_in,
                              void* d_out, int out_size)
{
    const float* x  = (const float*)d_in[0];
    const float* w1 = (const float*)d_in[1];
    const float* b1 = (const float*)d_in[2];
    const float* w2 = (const float*)d_in[3];
    const float* b2 = (const float*)d_in[4];
    float* out = (float*)d_out;

    cudaFuncSetAttribute((const void*)rfftWT_k,   cudaFuncAttributeMaxDynamicSharedMemorySize, RW_TOT);
    cudaFuncSetAttribute((const void*)fftHT_k<0>, cudaFuncAttributeMaxDynamicSharedMemorySize, FH_TOT);
    cudaFuncSetAttribute((const void*)fftHT_k<1>, cudaFuncAttributeMaxDynamicSharedMemorySize, FH_TOT);
    cudaFuncSetAttribute((const void*)irfftWT_k,  cudaFuncAttributeMaxDynamicSharedMemorySize, IW_TOT);
    cudaFuncSetAttribute((const void*)gemmM_k<1>, cudaFuncAttributeMaxDynamicSharedMemorySize, GEMM_SMEM);
    cudaFuncSetAttribute((const void*)gemmM_k<2>, cudaFuncAttributeMaxDynamicSharedMemorySize, GEMM_SMEM);

    init_k<<<512, 256>>>(w1, b1, w2, b2);
    rfftWT_k<<<dim3(BB*HH, 3), 256, RW_TOT>>>(x);
    fftHT_k<0><<<dim3(BB, 58), 256, FH_TOT>>>();
    gemmM_k<1><<<dim3(406, 3, NBLK), 256, GEMM_SMEM>>>();
    gemmM_k<2><<<dim3(406, 3, NBLK), 256, GEMM_SMEM>>>();
    fftHT_k<1><<<dim3(BB, 58), 256, FH_TOT>>>();
    irfftWT_k<<<dim3(BB*HH, 3), 256, IW_TOT>>>(out);
}